// round 1
// baseline (speedup 1.0000x reference)
#include <cuda_runtime.h>
#include <math.h>

#define NB 4
#define CH 128
#define LL 4096
#define SCALE 0.08838834764831845f  // 1/sqrt(128)

// Scratch (allocation-free: static device globals)
__device__ float g_q[NB * CH * LL];
__device__ float g_k[NB * CH * LL];
__device__ float g_v[NB * CH * LL];
__device__ float g_s[(size_t)NB * LL * LL];   // 268 MB raw scaled scores
__device__ float g_rmax[NB * LL];
__device__ float g_rsum[NB * LL];

// ---------------------------------------------------------------------------
// Kernel A: q/k/v = W @ x + b   (per batch: [128,128] x [128,4096])
// grid (32, 4), 256 threads, dyn smem 128 KB (x tile + W tile)
// ---------------------------------------------------------------------------
__global__ __launch_bounds__(256) void qkv_kernel(
    const float* __restrict__ x,
    const float* __restrict__ Wq, const float* __restrict__ bq,
    const float* __restrict__ Wk, const float* __restrict__ bk,
    const float* __restrict__ Wv, const float* __restrict__ bv)
{
    extern __shared__ float sm[];
    float* xs = sm;            // [128][128]
    float* ws = sm + 128*128;  // [128][128]
    int n  = blockIdx.y;
    int m0 = blockIdx.x * 128;
    int t  = threadIdx.x;
    const float* xb = x + (size_t)n * CH * LL;

#pragma unroll
    for (int i = 0; i < 16; i++) {
        int idx = i * 256 + t;          // 4096 float4
        int c = idx >> 5, m4 = idx & 31;
        ((float4*)xs)[c * 32 + m4] =
            *((const float4*)(xb + (size_t)c * LL + m0) + m4);
    }

    int o0 = (t >> 4) * 8;
    int mm = (t & 15) * 8;
    const float* Wmat[3] = {Wq, Wk, Wv};
    const float* Bvec[3] = {bq, bk, bv};
    float* Outp[3];
    Outp[0] = g_q; Outp[1] = g_k; Outp[2] = g_v;

    for (int w = 0; w < 3; w++) {
        __syncthreads();
#pragma unroll
        for (int i = 0; i < 16; i++) {
            int idx = i * 256 + t;
            ((float4*)ws)[idx] = ((const float4*)Wmat[w])[idx];
        }
        __syncthreads();

        float acc[8][8];
#pragma unroll
        for (int i = 0; i < 8; i++)
#pragma unroll
            for (int j = 0; j < 8; j++) acc[i][j] = 0.f;

        for (int c = 0; c < 128; c++) {
            float a[8];
#pragma unroll
            for (int i = 0; i < 8; i++) a[i] = ws[(o0 + i) * 128 + c];
            float4 b0 = *(const float4*)&xs[c * 128 + mm];
            float4 b1 = *(const float4*)&xs[c * 128 + mm + 4];
            float b[8] = {b0.x, b0.y, b0.z, b0.w, b1.x, b1.y, b1.z, b1.w};
#pragma unroll
            for (int i = 0; i < 8; i++)
#pragma unroll
                for (int j = 0; j < 8; j++)
                    acc[i][j] = fmaf(a[i], b[j], acc[i][j]);
        }

        float* ob = Outp[w] + (size_t)n * CH * LL;
#pragma unroll
        for (int i = 0; i < 8; i++) {
            float bias = Bvec[w][o0 + i];
            float4 r0 = make_float4(acc[i][0] + bias, acc[i][1] + bias,
                                    acc[i][2] + bias, acc[i][3] + bias);
            float4 r1 = make_float4(acc[i][4] + bias, acc[i][5] + bias,
                                    acc[i][6] + bias, acc[i][7] + bias);
            *(float4*)(ob + (size_t)(o0 + i) * LL + m0 + mm)     = r0;
            *(float4*)(ob + (size_t)(o0 + i) * LL + m0 + mm + 4) = r1;
        }
    }
}

// ---------------------------------------------------------------------------
// Kernel B: scores[l,m] = scale * sum_c k[c,l]*q[c,m]; write raw scores,
// maintain online row (max, sum-exp) over m. grid (64, 4), 128 threads.
// Block: 64 l-rows x all m in 128-wide chunks. dyn smem 96 KB.
// ---------------------------------------------------------------------------
__global__ __launch_bounds__(128) void scores_kernel()
{
    extern __shared__ float sm[];
    float* ks = sm;            // [128][64]  k tile (persistent)
    float* qs = sm + 128*64;   // [128][128] q chunk (streamed)
    int n  = blockIdx.y;
    int l0 = blockIdx.x * 64;
    int t  = threadIdx.x;
    const float* kb = g_k + (size_t)n * CH * LL;
    const float* qb = g_q + (size_t)n * CH * LL;

#pragma unroll
    for (int i = 0; i < 16; i++) {
        int idx = i * 128 + t;          // 2048 float4
        int c = idx >> 4, l4 = idx & 15;
        ((float4*)ks)[c * 16 + l4] =
            *((const float4*)(kb + (size_t)c * LL + l0) + l4);
    }

    int r0 = (t >> 4) * 8;   // 8 row-groups x 8 rows = 64
    int cg = (t & 15);       // 16 col-groups x 8 cols = 128

    float rM[8], rS[8];
#pragma unroll
    for (int i = 0; i < 8; i++) { rM[i] = -1e30f; rS[i] = 0.f; }

    for (int mc = 0; mc < 32; mc++) {
        int m0 = mc * 128;
        __syncthreads();
#pragma unroll
        for (int i = 0; i < 32; i++) {
            int idx = i * 128 + t;      // 4096 float4
            int c = idx >> 5, m4 = idx & 31;
            ((float4*)qs)[c * 32 + m4] =
                *((const float4*)(qb + (size_t)c * LL + m0) + m4);
        }
        __syncthreads();

        float acc[8][8];
#pragma unroll
        for (int i = 0; i < 8; i++)
#pragma unroll
            for (int j = 0; j < 8; j++) acc[i][j] = 0.f;

        for (int c = 0; c < 128; c++) {
            float4 a0 = *(const float4*)&ks[c * 64 + r0];
            float4 a1 = *(const float4*)&ks[c * 64 + r0 + 4];
            float4 b0 = *(const float4*)&qs[c * 128 + cg * 8];
            float4 b1 = *(const float4*)&qs[c * 128 + cg * 8 + 4];
            float a[8] = {a0.x, a0.y, a0.z, a0.w, a1.x, a1.y, a1.z, a1.w};
            float b[8] = {b0.x, b0.y, b0.z, b0.w, b1.x, b1.y, b1.z, b1.w};
#pragma unroll
            for (int i = 0; i < 8; i++)
#pragma unroll
                for (int j = 0; j < 8; j++)
                    acc[i][j] = fmaf(a[i], b[j], acc[i][j]);
        }

#pragma unroll
        for (int i = 0; i < 8; i++) {
            float mx = -1e30f;
#pragma unroll
            for (int j = 0; j < 8; j++) {
                acc[i][j] *= SCALE;
                mx = fmaxf(mx, acc[i][j]);
            }
#pragma unroll
            for (int s = 1; s < 16; s <<= 1)
                mx = fmaxf(mx, __shfl_xor_sync(0xffffffffu, mx, s));
            float nm = fmaxf(rM[i], mx);
            float ps = 0.f;
#pragma unroll
            for (int j = 0; j < 8; j++) ps += __expf(acc[i][j] - nm);
#pragma unroll
            for (int s = 1; s < 16; s <<= 1)
                ps += __shfl_xor_sync(0xffffffffu, ps, s);
            rS[i] = rS[i] * __expf(rM[i] - nm) + ps;
            rM[i] = nm;

            float* srow = g_s + ((size_t)(n * LL + l0 + r0 + i)) * LL + m0 + cg * 8;
            *(float4*)srow =
                make_float4(acc[i][0], acc[i][1], acc[i][2], acc[i][3]);
            *(float4*)(srow + 4) =
                make_float4(acc[i][4], acc[i][5], acc[i][6], acc[i][7]);
        }
    }

    if (cg == 0) {
#pragma unroll
        for (int i = 0; i < 8; i++) {
            g_rmax[n * LL + l0 + r0 + i] = rM[i];
            g_rsum[n * LL + l0 + r0 + i] = rS[i];
        }
    }
}

// ---------------------------------------------------------------------------
// Kernel C: out[c,m] = x[c,m] + sum_l v[c,l]*exp(s[l,m]-M[l])/D[l]
// grid (32, 4), 256 threads, dyn smem ~64.5 KB. Output tile 128x128.
// ---------------------------------------------------------------------------
__global__ __launch_bounds__(256) void attn_kernel(
    const float* __restrict__ x, float* __restrict__ out)
{
    extern __shared__ float sm[];
    float* wsm = sm;                   // [64][128] softmax weights chunk
    float* vs  = sm + 64*128;          // [128][64] v chunk
    float* Ml  = sm + 64*128 + 128*64; // [64]
    float* Di  = Ml + 64;              // [64]
    int n  = blockIdx.y;
    int m0 = blockIdx.x * 128;
    int t  = threadIdx.x;
    int c0 = (t >> 4) * 8;
    int mg = (t & 15) * 8;
    const float* vb = g_v + (size_t)n * CH * LL;

    float acc[8][8];
#pragma unroll
    for (int i = 0; i < 8; i++)
#pragma unroll
        for (int j = 0; j < 8; j++) acc[i][j] = 0.f;

    for (int lc = 0; lc < 64; lc++) {
        int l0 = lc * 64;
        __syncthreads();
        if (t < 64) {
            Ml[t] = g_rmax[n * LL + l0 + t];
            Di[t] = 1.0f / g_rsum[n * LL + l0 + t];
        }
#pragma unroll
        for (int i = 0; i < 8; i++) {
            int idx = i * 256 + t;      // 2048 float4
            int c = idx >> 4, l4 = idx & 15;
            ((float4*)vs)[c * 16 + l4] =
                *((const float4*)(vb + (size_t)c * LL + l0) + l4);
        }
        __syncthreads();

        // Build weights chunk: w[l][m] = exp(s - M[l]) * invD[l]
#pragma unroll
        for (int i = 0; i < 8; i++) {
            int idx = i * 256 + t;      // 2048 float4 covering 64x128
            int l = idx >> 5, m4 = idx & 31;
            float4 s4 = *((const float4*)(g_s + ((size_t)(n * LL + l0 + l)) * LL + m0) + m4);
            float mlv = Ml[l], dv = Di[l];
            float4 w4;
            w4.x = __expf(s4.x - mlv) * dv;
            w4.y = __expf(s4.y - mlv) * dv;
            w4.z = __expf(s4.z - mlv) * dv;
            w4.w = __expf(s4.w - mlv) * dv;
            ((float4*)wsm)[idx] = w4;
        }
        __syncthreads();

        for (int l = 0; l < 64; l++) {
            float a[8];
#pragma unroll
            for (int i = 0; i < 8; i++) a[i] = vs[(c0 + i) * 64 + l];
            float4 b0 = *(const float4*)&wsm[l * 128 + mg];
            float4 b1 = *(const float4*)&wsm[l * 128 + mg + 4];
            float b[8] = {b0.x, b0.y, b0.z, b0.w, b1.x, b1.y, b1.z, b1.w};
#pragma unroll
            for (int i = 0; i < 8; i++)
#pragma unroll
                for (int j = 0; j < 8; j++)
                    acc[i][j] = fmaf(a[i], b[j], acc[i][j]);
        }
    }

    const float* xb = x + (size_t)n * CH * LL;
    float* ob = out + (size_t)n * CH * LL;
#pragma unroll
    for (int i = 0; i < 8; i++) {
        size_t off = (size_t)(c0 + i) * LL + m0 + mg;
        float4 x0 = *(const float4*)(xb + off);
        float4 x1 = *(const float4*)(xb + off + 4);
        float4 r0 = make_float4(acc[i][0] + x0.x, acc[i][1] + x0.y,
                                acc[i][2] + x0.z, acc[i][3] + x0.w);
        float4 r1 = make_float4(acc[i][4] + x1.x, acc[i][5] + x1.y,
                                acc[i][6] + x1.z, acc[i][7] + x1.w);
        *(float4*)(ob + off)     = r0;
        *(float4*)(ob + off + 4) = r1;
    }
}

// ---------------------------------------------------------------------------
extern "C" void kernel_launch(void* const* d_in, const int* in_sizes, int n_in,
                              void* d_out, int out_size)
{
    const float* x  = (const float*)d_in[0];
    const float* Wq = (const float*)d_in[1];
    const float* bq = (const float*)d_in[2];
    const float* Wk = (const float*)d_in[3];
    const float* bk = (const float*)d_in[4];
    const float* Wv = (const float*)d_in[5];
    const float* bv = (const float*)d_in[6];
    float* out = (float*)d_out;

    cudaFuncSetAttribute(qkv_kernel,    cudaFuncAttributeMaxDynamicSharedMemorySize, 131072);
    cudaFuncSetAttribute(scores_kernel, cudaFuncAttributeMaxDynamicSharedMemorySize, 98304);
    cudaFuncSetAttribute(attn_kernel,   cudaFuncAttributeMaxDynamicSharedMemorySize, 66560);

    qkv_kernel<<<dim3(32, 4), 256, 131072>>>(x, Wq, bq, Wk, bk, Wv, bv);
    scores_kernel<<<dim3(64, 4), 128, 98304>>>();
    attn_kernel<<<dim3(32, 4), 256, 66560>>>(x, out);
}

// round 3
// speedup vs baseline: 4.6261x; 4.6261x over previous
#include <cuda_runtime.h>
#include <cuda_bf16.h>
#include <math.h>
#include <stdint.h>

#define NB 4
#define CH 128
#define LL 4096
#define SCALE 0.08838834764831845f  // 1/sqrt(128)

// ---------------------------------------------------------------------------
// Scratch (allocation-free: static device globals)
// ---------------------------------------------------------------------------
__device__ __nv_bfloat16  g_qT[(size_t)NB * LL * CH];  // q^T [n][m][c]
__device__ __nv_bfloat16  g_kT[(size_t)NB * LL * CH];  // k^T [n][l][c]
__device__ __nv_bfloat16  g_vB[(size_t)NB * CH * LL];  // v   [n][c][l]
__device__ float          g_mprime[NB * LL];           // rowmax + ln(rowsum)

// ---------------------------------------------------------------------------
// Helpers
// ---------------------------------------------------------------------------
__device__ __forceinline__ uint32_t smem_u32(const void* p) {
    uint32_t a;
    asm("{ .reg .u64 t; cvta.to.shared.u64 t, %1; cvt.u32.u64 %0, t; }"
        : "=r"(a) : "l"(p));
    return a;
}

__device__ __forceinline__ uint32_t pk_bf16(float a, float b) {
    __nv_bfloat162 t = __floats2bfloat162_rn(a, b);
    return *reinterpret_cast<uint32_t*>(&t);
}

// Swizzled smem tile: 128 rows x 128 bf16 (256B/row = 16 chunks of 16B).
// chunk index XORed with (row & 7) -> conflict-free ldmatrix + stores.
__device__ __forceinline__ uint32_t sw_off(int row, int ch) {
    return (uint32_t)row * 256u + (uint32_t)((ch ^ (row & 7)) << 4);
}

// ldmatrix x4
__device__ __forceinline__ void ldsm_x4(uint32_t addr, uint32_t* r) {
    asm volatile("ldmatrix.sync.aligned.m8n8.x4.shared.b16 {%0,%1,%2,%3}, [%4];"
        : "=r"(r[0]), "=r"(r[1]), "=r"(r[2]), "=r"(r[3]) : "r"(addr));
}

// A-fragment address (16x16 tile at rows r0.., k-chunk kk) for lane
__device__ __forceinline__ uint32_t a_addr(uint32_t tb, int r0, int kk, int lane) {
    int r  = r0 + (lane & 7) + ((lane & 8) ? 8 : 0);
    int ch = kk * 2 + (lane >> 4);
    return tb + sw_off(r, ch);
}
// B-fragment x4 address: two n8 tiles (rows n0..n0+15 of B^T), k-step kk
__device__ __forceinline__ uint32_t b_addr(uint32_t tb, int n0, int kk, int lane) {
    int g  = lane >> 3;
    int r  = n0 + (lane & 7) + ((g & 2) ? 8 : 0);
    int ch = kk * 2 + (g & 1);
    return tb + sw_off(r, ch);
}

__device__ __forceinline__ void mma_bf16(float* d, const uint32_t* a, const uint32_t* b) {
    asm volatile(
        "mma.sync.aligned.m16n8k16.row.col.f32.bf16.bf16.f32 "
        "{%0,%1,%2,%3}, {%4,%5,%6,%7}, {%8,%9}, {%0,%1,%2,%3};"
        : "+f"(d[0]), "+f"(d[1]), "+f"(d[2]), "+f"(d[3])
        : "r"(a[0]), "r"(a[1]), "r"(a[2]), "r"(a[3]), "r"(b[0]), "r"(b[1]));
}

// ---------------------------------------------------------------------------
// Kernel A: q/k/v = W @ x + b (fp32 SIMT), emit qT/kT [L][C] bf16, v [C][L] bf16
// grid (32, 4), 256 threads, dyn smem 160 KB
// ---------------------------------------------------------------------------
__global__ __launch_bounds__(256) void qkv_kernel(
    const float* __restrict__ x,
    const float* __restrict__ Wq, const float* __restrict__ bq,
    const float* __restrict__ Wk, const float* __restrict__ bk,
    const float* __restrict__ Wv, const float* __restrict__ bv)
{
    extern __shared__ float sm[];
    float* xs = sm;                     // [128][128] fp32 x tile
    float* ws = sm + 128 * 128;         // [128][128] fp32 W tile
    char*  stage = (char*)(sm + 2 * 128 * 128);  // 32KB bf16 transpose stage
    int n  = blockIdx.y;
    int m0 = blockIdx.x * 128;
    int t  = threadIdx.x;
    const float* xb = x + (size_t)n * CH * LL;

#pragma unroll
    for (int i = 0; i < 16; i++) {
        int idx = i * 256 + t;
        int c = idx >> 5, m4 = idx & 31;
        ((float4*)xs)[c * 32 + m4] =
            *((const float4*)(xb + (size_t)c * LL + m0) + m4);
    }

    int o0 = (t >> 4) * 8;
    int mm = (t & 15) * 8;
    const float* Wmat[3] = {Wq, Wk, Wv};
    const float* Bvec[3] = {bq, bk, bv};

    for (int w = 0; w < 3; w++) {
        __syncthreads();
#pragma unroll
        for (int i = 0; i < 16; i++) {
            int idx = i * 256 + t;
            ((float4*)ws)[idx] = ((const float4*)Wmat[w])[idx];
        }
        __syncthreads();

        float acc[8][8];
#pragma unroll
        for (int i = 0; i < 8; i++)
#pragma unroll
            for (int j = 0; j < 8; j++) acc[i][j] = 0.f;

        for (int c = 0; c < 128; c++) {
            float a[8];
#pragma unroll
            for (int i = 0; i < 8; i++) a[i] = ws[(o0 + i) * 128 + c];
            float4 b0 = *(const float4*)&xs[c * 128 + mm];
            float4 b1 = *(const float4*)&xs[c * 128 + mm + 4];
            float b[8] = {b0.x, b0.y, b0.z, b0.w, b1.x, b1.y, b1.z, b1.w};
#pragma unroll
            for (int i = 0; i < 8; i++)
#pragma unroll
                for (int j = 0; j < 8; j++)
                    acc[i][j] = fmaf(a[i], b[j], acc[i][j]);
        }

        float bb[8];
#pragma unroll
        for (int i = 0; i < 8; i++) bb[i] = Bvec[w][o0 + i];

        if (w < 2) {
            __syncthreads();
#pragma unroll
            for (int j = 0; j < 8; j++) {
                int m = mm + j;
                uint4 u;
                u.x = pk_bf16(acc[0][j] + bb[0], acc[1][j] + bb[1]);
                u.y = pk_bf16(acc[2][j] + bb[2], acc[3][j] + bb[3]);
                u.z = pk_bf16(acc[4][j] + bb[4], acc[5][j] + bb[5]);
                u.w = pk_bf16(acc[6][j] + bb[6], acc[7][j] + bb[7]);
                *(uint4*)(stage + (size_t)m * 256 + o0 * 2) = u;
            }
            __syncthreads();
            __nv_bfloat16* dst = (w == 0 ? g_qT : g_kT) + ((size_t)n * LL + m0) * CH;
#pragma unroll
            for (int i = 0; i < 8; i++) {
                int idx = i * 256 + t;
                int row = idx >> 4, g = idx & 15;
                *(uint4*)(dst + (size_t)row * CH + g * 8) = ((uint4*)stage)[idx];
            }
        } else {
#pragma unroll
            for (int i = 0; i < 8; i++) {
                uint4 u;
                u.x = pk_bf16(acc[i][0] + bb[i], acc[i][1] + bb[i]);
                u.y = pk_bf16(acc[i][2] + bb[i], acc[i][3] + bb[i]);
                u.z = pk_bf16(acc[i][4] + bb[i], acc[i][5] + bb[i]);
                u.w = pk_bf16(acc[i][6] + bb[i], acc[i][7] + bb[i]);
                *(uint4*)(g_vB + ((size_t)n * CH + o0 + i) * LL + m0 + mm) = u;
            }
        }
    }
}

// ---------------------------------------------------------------------------
// Kernel B: softmax row stats M'[l] = max_m(s) + ln(sum_m exp(s-max))
// S = scale*K^T Q via mma.sync. CTA = (128-l tile, batch), 256 thr (8 warps).
// Warp w owns l rows w*16. smem: kT tile (persistent) + qT chunk (streamed).
// ---------------------------------------------------------------------------
__global__ __launch_bounds__(256, 1) void stats_kernel()
{
    extern __shared__ char smc[];
    char* kt = smc;              // 32KB
    char* qt = smc + 32768;      // 32KB
    uint32_t ktb = smem_u32(kt);
    uint32_t qtb = smem_u32(qt);

    int n  = blockIdx.y;
    int l0 = blockIdx.x * 128;
    int t  = threadIdx.x;
    int lane = t & 31, w = t >> 5;
    int lw = w * 16;

    // load kT tile (rows l0..l0+127)
    const uint4* ksrc = (const uint4*)(g_kT + ((size_t)n * LL + l0) * CH);
#pragma unroll
    for (int i = t; i < 2048; i += 256) {
        int row = i >> 4, ch = i & 15;
        *(uint4*)(kt + sw_off(row, ch)) = ksrc[row * 16 + ch];
    }
    __syncthreads();

    // persistent A fragments: kT rows lw..lw+15
    uint32_t af[8][4];
#pragma unroll
    for (int kk = 0; kk < 8; kk++) ldsm_x4(a_addr(ktb, lw, kk, lane), af[kk]);

    const uint4* qsrc = (const uint4*)(g_qT + (size_t)n * LL * CH);

    float rM0 = -3.0e38f, rS0 = 0.f, rM1 = -3.0e38f, rS1 = 0.f;

    for (int mc = 0; mc < 32; mc++) {
        if (mc) __syncthreads();
#pragma unroll
        for (int i = t; i < 2048; i += 256) {
            int row = i >> 4, ch = i & 15;
            *(uint4*)(qt + sw_off(row, ch)) = qsrc[(mc * 128 + row) * 16 + ch];
        }
        __syncthreads();

        float sacc[16][4];
#pragma unroll
        for (int j = 0; j < 16; j++)
#pragma unroll
            for (int q = 0; q < 4; q++) sacc[j][q] = 0.f;

#pragma unroll
        for (int kk = 0; kk < 8; kk++) {
#pragma unroll
            for (int jp = 0; jp < 8; jp++) {
                uint32_t b[4];
                ldsm_x4(b_addr(qtb, jp * 16, kk, lane), b);
                mma_bf16(sacc[jp * 2],     af[kk], b);
                mma_bf16(sacc[jp * 2 + 1], af[kk], b + 2);
            }
        }

        // online stats: row lw+lane/4 (d0,d1), row lw+lane/4+8 (d2,d3)
        float mx0 = -3.0e38f, mx1 = -3.0e38f;
#pragma unroll
        for (int j = 0; j < 16; j++) {
            mx0 = fmaxf(mx0, fmaxf(sacc[j][0], sacc[j][1]));
            mx1 = fmaxf(mx1, fmaxf(sacc[j][2], sacc[j][3]));
        }
        float nm0 = fmaxf(rM0, mx0 * SCALE);
        float nm1 = fmaxf(rM1, mx1 * SCALE);
        float s0 = 0.f, s1 = 0.f;
#pragma unroll
        for (int j = 0; j < 16; j++) {
            s0 += __expf(sacc[j][0] * SCALE - nm0) + __expf(sacc[j][1] * SCALE - nm0);
            s1 += __expf(sacc[j][2] * SCALE - nm1) + __expf(sacc[j][3] * SCALE - nm1);
        }
        rS0 = rS0 * __expf(rM0 - nm0) + s0; rM0 = nm0;
        rS1 = rS1 * __expf(rM1 - nm1) + s1; rM1 = nm1;
    }

    // reduce across the 4 lanes of each quad
#pragma unroll
    for (int d = 1; d < 4; d <<= 1) {
        float oM = __shfl_xor_sync(0xffffffffu, rM0, d);
        float oS = __shfl_xor_sync(0xffffffffu, rS0, d);
        float nm = fmaxf(rM0, oM);
        rS0 = rS0 * __expf(rM0 - nm) + oS * __expf(oM - nm);
        rM0 = nm;
        oM = __shfl_xor_sync(0xffffffffu, rM1, d);
        oS = __shfl_xor_sync(0xffffffffu, rS1, d);
        nm = fmaxf(rM1, oM);
        rS1 = rS1 * __expf(rM1 - nm) + oS * __expf(oM - nm);
        rM1 = nm;
    }
    if ((lane & 3) == 0) {
        int r = l0 + lw + (lane >> 2);
        g_mprime[n * LL + r]     = rM0 + __logf(rS0);
        g_mprime[n * LL + r + 8] = rM1 + __logf(rS1);
    }
}

// ---------------------------------------------------------------------------
// Kernel C: out[c,m] = x[c,m] + sum_l v[c,l]*exp(s[l,m]-M'[l]).
// CTA = (128-m tile, batch), 256 threads (8 warps).
// Per l-chunk(128): S^T tile via mma (A=qT persistent, B=kT chunk),
// exp in regs -> bf16 P^T smem tile -> mma2 (A=v chunk, B=P^T) accumulating
// out[c][m] in registers across all 32 chunks.
// smem: qt 32K | kt 32K | vt 32K | pt 32K | mp 512B
// ---------------------------------------------------------------------------
__global__ __launch_bounds__(256, 1) void attn_kernel(
    const float* __restrict__ x, float* __restrict__ out)
{
    extern __shared__ char smc[];
    char* qt = smc;
    char* kt = smc + 32768;
    char* vt = smc + 65536;
    char* pt = smc + 98304;
    float* mpS = (float*)(smc + 131072);
    uint32_t qtb = smem_u32(qt);
    uint32_t ktb = smem_u32(kt);
    uint32_t vtb = smem_u32(vt);
    uint32_t ptb = smem_u32(pt);

    int n  = blockIdx.y;
    int m0 = blockIdx.x * 128;
    int t  = threadIdx.x;
    int lane = t & 31, w = t >> 5;
    int rw = w * 16;

    // load qT tile (rows m0..m0+127) persistent
    const uint4* qsrc = (const uint4*)(g_qT + ((size_t)n * LL + m0) * CH);
#pragma unroll
    for (int i = t; i < 2048; i += 256) {
        int row = i >> 4, ch = i & 15;
        *(uint4*)(qt + sw_off(row, ch)) = qsrc[row * 16 + ch];
    }
    __syncthreads();

    uint32_t af[8][4];   // qT rows rw..rw+15 (persistent A for S^T mma)
#pragma unroll
    for (int kk = 0; kk < 8; kk++) ldsm_x4(a_addr(qtb, rw, kk, lane), af[kk]);

    const uint4* ksrc = (const uint4*)(g_kT + (size_t)n * LL * CH);
    const uint4* vsrc = (const uint4*)(g_vB + (size_t)n * CH * LL); // row pitch 512 u4

    float oacc[16][4];
#pragma unroll
    for (int j = 0; j < 16; j++)
#pragma unroll
        for (int q = 0; q < 4; q++) oacc[j][q] = 0.f;

    int mrow = rw + (lane >> 2);     // m row for S^T d-frags
    int ecol = (lane & 3) * 2;

    for (int lc = 0; lc < 32; lc++) {
        __syncthreads();
#pragma unroll
        for (int i = t; i < 2048; i += 256) {
            int row = i >> 4, ch = i & 15;
            *(uint4*)(kt + sw_off(row, ch)) = ksrc[(lc * 128 + row) * 16 + ch];
            *(uint4*)(vt + sw_off(row, ch)) = vsrc[row * 512 + lc * 16 + ch];
        }
        if (t < 128) mpS[t] = g_mprime[n * LL + lc * 128 + t];
        __syncthreads();

        // S^T tile: rows m (warp's 16), cols l (128)
        float sacc[16][4];
#pragma unroll
        for (int j = 0; j < 16; j++)
#pragma unroll
            for (int q = 0; q < 4; q++) sacc[j][q] = 0.f;

#pragma unroll
        for (int kk = 0; kk < 8; kk++) {
#pragma unroll
            for (int jp = 0; jp < 8; jp++) {
                uint32_t b[4];
                ldsm_x4(b_addr(ktb, jp * 16, kk, lane), b);
                mma_bf16(sacc[jp * 2],     af[kk], b);
                mma_bf16(sacc[jp * 2 + 1], af[kk], b + 2);
            }
        }

        // exp -> P^T [m][l] bf16 smem
#pragma unroll
        for (int j = 0; j < 16; j++) {
            int l = j * 8 + ecol;
            float mp0 = mpS[l], mp1 = mpS[l + 1];
            uint32_t p01 = pk_bf16(__expf(sacc[j][0] * SCALE - mp0),
                                   __expf(sacc[j][1] * SCALE - mp1));
            uint32_t p23 = pk_bf16(__expf(sacc[j][2] * SCALE - mp0),
                                   __expf(sacc[j][3] * SCALE - mp1));
            *(uint32_t*)(pt + sw_off(mrow,     j) + ecol * 2) = p01;
            *(uint32_t*)(pt + sw_off(mrow + 8, j) + ecol * 2) = p23;
        }
        __syncthreads();

        // mma2: out[c][m] += v[c][l-chunk] * P[l-chunk][m]
        uint32_t af2[8][4];  // v rows rw..rw+15 (c rows)
#pragma unroll
        for (int kk = 0; kk < 8; kk++) ldsm_x4(a_addr(vtb, rw, kk, lane), af2[kk]);
#pragma unroll
        for (int kk = 0; kk < 8; kk++) {
#pragma unroll
            for (int jp = 0; jp < 8; jp++) {
                uint32_t b[4];
                ldsm_x4(b_addr(ptb, jp * 16, kk, lane), b);
                mma_bf16(oacc[jp * 2],     af2[kk], b);
                mma_bf16(oacc[jp * 2 + 1], af2[kk], b + 2);
            }
        }
    }

    // epilogue: d-frags rows c = rw+lane/4 (+8), cols m = j*8 + ecol
    int c0 = rw + (lane >> 2);
    const float* xb = x + (size_t)n * CH * LL;
    float* ob = out + (size_t)n * CH * LL;
#pragma unroll
    for (int j = 0; j < 16; j++) {
        size_t off0 = (size_t)c0 * LL + m0 + j * 8 + ecol;
        size_t off1 = (size_t)(c0 + 8) * LL + m0 + j * 8 + ecol;
        float2 x0 = *(const float2*)(xb + off0);
        float2 x1 = *(const float2*)(xb + off1);
        float2 r0 = make_float2(oacc[j][0] + x0.x, oacc[j][1] + x0.y);
        float2 r1 = make_float2(oacc[j][2] + x1.x, oacc[j][3] + x1.y);
        *(float2*)(ob + off0) = r0;
        *(float2*)(ob + off1) = r1;
    }
}

// ---------------------------------------------------------------------------
extern "C" void kernel_launch(void* const* d_in, const int* in_sizes, int n_in,
                              void* d_out, int out_size)
{
    const float* x  = (const float*)d_in[0];
    const float* Wq = (const float*)d_in[1];
    const float* bq = (const float*)d_in[2];
    const float* Wk = (const float*)d_in[3];
    const float* bk = (const float*)d_in[4];
    const float* Wv = (const float*)d_in[5];
    const float* bv = (const float*)d_in[6];
    float* out = (float*)d_out;

    cudaFuncSetAttribute(qkv_kernel,   cudaFuncAttributeMaxDynamicSharedMemorySize, 163840);
    cudaFuncSetAttribute(stats_kernel, cudaFuncAttributeMaxDynamicSharedMemorySize, 65536);
    cudaFuncSetAttribute(attn_kernel,  cudaFuncAttributeMaxDynamicSharedMemorySize, 131584);

    qkv_kernel<<<dim3(32, 4), 256, 163840>>>(x, Wq, bq, Wk, bk, Wv, bv);
    stats_kernel<<<dim3(32, 4), 256, 65536>>>();
    attn_kernel<<<dim3(32, 4), 256, 131584>>>(x, out);
}

// round 4
// speedup vs baseline: 5.2941x; 1.1444x over previous
#include <cuda_runtime.h>
#include <cuda_bf16.h>
#include <stdint.h>

#define NB 4
#define CH 128
#define LL 4096
#define SCALE 0.08838834764831845f  // 1/sqrt(128)

// ---------------------------------------------------------------------------
// Scratch (allocation-free: static device globals)
// ---------------------------------------------------------------------------
__device__ __nv_bfloat16  g_xT[(size_t)NB * LL * CH];  // x^T [n][m][c]
__device__ __nv_bfloat16  g_qT[(size_t)NB * LL * CH];  // q^T [n][m][c]
__device__ __nv_bfloat16  g_kT[(size_t)NB * LL * CH];  // k^T [n][l][c], pre-scaled
__device__ __nv_bfloat16  g_vB[(size_t)NB * CH * LL];  // v   [n][c][l]
__device__ float          g_mprime[NB * LL];           // rowmax + ln(rowsum)

// ---------------------------------------------------------------------------
// Helpers
// ---------------------------------------------------------------------------
__device__ __forceinline__ uint32_t smem_u32(const void* p) {
    uint32_t a;
    asm("{ .reg .u64 t; cvta.to.shared.u64 t, %1; cvt.u32.u64 %0, t; }"
        : "=r"(a) : "l"(p));
    return a;
}

__device__ __forceinline__ uint32_t pk_bf16(float a, float b) {
    __nv_bfloat162 t = __floats2bfloat162_rn(a, b);
    return *reinterpret_cast<uint32_t*>(&t);
}

// Swizzled smem tile: rows x 128 bf16 (256B/row = 16 chunks of 16B).
__device__ __forceinline__ uint32_t sw_off(int row, int ch) {
    return (uint32_t)row * 256u + (uint32_t)((ch ^ (row & 7)) << 4);
}

__device__ __forceinline__ void ldsm_x4(uint32_t addr, uint32_t* r) {
    asm volatile("ldmatrix.sync.aligned.m8n8.x4.shared.b16 {%0,%1,%2,%3}, [%4];"
        : "=r"(r[0]), "=r"(r[1]), "=r"(r[2]), "=r"(r[3]) : "r"(addr));
}

__device__ __forceinline__ uint32_t a_addr(uint32_t tb, int r0, int kk, int lane) {
    int r  = r0 + (lane & 7) + ((lane & 8) ? 8 : 0);
    int ch = kk * 2 + (lane >> 4);
    return tb + sw_off(r, ch);
}
__device__ __forceinline__ uint32_t b_addr(uint32_t tb, int n0, int kk, int lane) {
    int g  = lane >> 3;
    int r  = n0 + (lane & 7) + ((g & 2) ? 8 : 0);
    int ch = kk * 2 + (g & 1);
    return tb + sw_off(r, ch);
}

__device__ __forceinline__ void mma_bf16(float* d, const uint32_t* a, const uint32_t* b) {
    asm volatile(
        "mma.sync.aligned.m16n8k16.row.col.f32.bf16.bf16.f32 "
        "{%0,%1,%2,%3}, {%4,%5,%6,%7}, {%8,%9}, {%0,%1,%2,%3};"
        : "+f"(d[0]), "+f"(d[1]), "+f"(d[2]), "+f"(d[3])
        : "r"(a[0]), "r"(a[1]), "r"(a[2]), "r"(a[3]), "r"(b[0]), "r"(b[1]));
}

// ---------------------------------------------------------------------------
// Kernel 0: transpose+convert  x [n][c][m] fp32 -> g_xT [n][m][c] bf16
// grid (128, 4), 256 threads
// ---------------------------------------------------------------------------
__global__ __launch_bounds__(256) void xpose_kernel(const float* __restrict__ x)
{
    __shared__ float ts[128][33];
    int n = blockIdx.y, m0 = blockIdx.x * 32, t = threadIdx.x;
    const float* xb = x + (size_t)n * CH * LL;
#pragma unroll
    for (int i = 0; i < 16; i++) {
        int c = i * 8 + (t >> 5);
        ts[c][t & 31] = xb[(size_t)c * LL + m0 + (t & 31)];
    }
    __syncthreads();
    int ml = t >> 3, cg = t & 7;
    __nv_bfloat16* dst = g_xT + ((size_t)n * LL + m0 + ml) * CH + cg * 16;
#pragma unroll
    for (int u = 0; u < 2; u++) {
        int cb = cg * 16 + u * 8;
        uint4 o;
        o.x = pk_bf16(ts[cb + 0][ml], ts[cb + 1][ml]);
        o.y = pk_bf16(ts[cb + 2][ml], ts[cb + 3][ml]);
        o.z = pk_bf16(ts[cb + 4][ml], ts[cb + 5][ml]);
        o.w = pk_bf16(ts[cb + 6][ml], ts[cb + 7][ml]);
        *(uint4*)(dst + u * 8) = o;
    }
}

// ---------------------------------------------------------------------------
// Kernel A: q/k/v via HMMA.  grid (64,4), 128 thr (4 warps).
// q,k: D[m][o] = xT[m][c] * W[o][c]^T -> direct qT/kT store (k pre-scaled).
// v:   D[o][m] = W[o][c] * xT[m][c]^T -> direct v[c][l] store.
// smem: xt 16KB | wt 32KB | bias 512B
// ---------------------------------------------------------------------------
__global__ __launch_bounds__(128) void qkv_kernel(
    const float* __restrict__ Wq, const float* __restrict__ bq,
    const float* __restrict__ Wk, const float* __restrict__ bk,
    const float* __restrict__ Wv, const float* __restrict__ bv)
{
    extern __shared__ char smc[];
    char* xt = smc;
    char* wt = smc + 16384;
    float* bias = (float*)(smc + 49152);
    uint32_t xtb = smem_u32(xt), wtb = smem_u32(wt);
    int n = blockIdx.y, m0 = blockIdx.x * 64, t = threadIdx.x;
    int lane = t & 31, w = t >> 5;
    int ecol = (lane & 3) * 2;

    const uint4* xsrc = (const uint4*)(g_xT + ((size_t)n * LL + m0) * CH);
#pragma unroll
    for (int i = t; i < 1024; i += 128) {
        int row = i >> 4, ch = i & 15;
        *(uint4*)(xt + sw_off(row, ch)) = xsrc[row * 16 + ch];
    }

    const float* Wm[3] = {Wq, Wk, Wv};
    const float* Bv[3] = {bq, bk, bv};

    for (int wi = 0; wi < 3; wi++) {
        __syncthreads();
#pragma unroll
        for (int i = t; i < 2048; i += 128) {
            int row = i >> 4, ch = i & 15;
            const float* src = Wm[wi] + row * 128 + ch * 8;
            float4 f0 = *(const float4*)src;
            float4 f1 = *(const float4*)(src + 4);
            uint4 u;
            u.x = pk_bf16(f0.x, f0.y); u.y = pk_bf16(f0.z, f0.w);
            u.z = pk_bf16(f1.x, f1.y); u.w = pk_bf16(f1.z, f1.w);
            *(uint4*)(wt + sw_off(row, ch)) = u;
        }
        bias[t] = Bv[wi][t];
        __syncthreads();

        if (wi < 2) {
            int lw = w * 16;
            float sacc[16][4];
#pragma unroll
            for (int j = 0; j < 16; j++)
#pragma unroll
                for (int q = 0; q < 4; q++) sacc[j][q] = 0.f;
#pragma unroll
            for (int kk = 0; kk < 8; kk++) {
                uint32_t a[4];
                ldsm_x4(a_addr(xtb, lw, kk, lane), a);
#pragma unroll
                for (int jp = 0; jp < 8; jp++) {
                    uint32_t b[4];
                    ldsm_x4(b_addr(wtb, jp * 16, kk, lane), b);
                    mma_bf16(sacc[jp * 2],     a, b);
                    mma_bf16(sacc[jp * 2 + 1], a, b + 2);
                }
            }
            int mrow = m0 + lw + (lane >> 2);
            __nv_bfloat16* dst = (wi == 0 ? g_qT : g_kT) + (size_t)n * LL * CH;
            float sc = (wi == 0) ? 1.0f : SCALE;
#pragma unroll
            for (int j = 0; j < 16; j++) {
                int o = (j >> 1) * 16 + (j & 1) * 8 + ecol;
                float b0 = bias[o], b1 = bias[o + 1];
                *(uint32_t*)(dst + (size_t)mrow * CH + o) =
                    pk_bf16((sacc[j][0] + b0) * sc, (sacc[j][1] + b1) * sc);
                *(uint32_t*)(dst + (size_t)(mrow + 8) * CH + o) =
                    pk_bf16((sacc[j][2] + b0) * sc, (sacc[j][3] + b1) * sc);
            }
        } else {
            int rw2 = w * 32;
            float vacc[16][4];
#pragma unroll
            for (int j = 0; j < 16; j++)
#pragma unroll
                for (int q = 0; q < 4; q++) vacc[j][q] = 0.f;
#pragma unroll
            for (int kk = 0; kk < 8; kk++) {
                uint32_t a0[4], a1[4];
                ldsm_x4(a_addr(wtb, rw2,      kk, lane), a0);
                ldsm_x4(a_addr(wtb, rw2 + 16, kk, lane), a1);
#pragma unroll
                for (int bp = 0; bp < 4; bp++) {
                    uint32_t b[4];
                    ldsm_x4(b_addr(xtb, bp * 16, kk, lane), b);
                    mma_bf16(vacc[bp * 2],         a0, b);
                    mma_bf16(vacc[bp * 2 + 1],     a0, b + 2);
                    mma_bf16(vacc[8 + bp * 2],     a1, b);
                    mma_bf16(vacc[8 + bp * 2 + 1], a1, b + 2);
                }
            }
#pragma unroll
            for (int set = 0; set < 2; set++) {
                int o = rw2 + set * 16 + (lane >> 2);
                float bo0 = bias[o], bo1 = bias[o + 8];
#pragma unroll
                for (int j = 0; j < 8; j++) {
                    int mc = m0 + j * 8 + ecol;
                    *(uint32_t*)(g_vB + ((size_t)n * CH + o) * LL + mc) =
                        pk_bf16(vacc[set * 8 + j][0] + bo0, vacc[set * 8 + j][1] + bo0);
                    *(uint32_t*)(g_vB + ((size_t)n * CH + o + 8) * LL + mc) =
                        pk_bf16(vacc[set * 8 + j][2] + bo1, vacc[set * 8 + j][3] + bo1);
                }
            }
        }
    }
}

// ---------------------------------------------------------------------------
// Kernel B: row stats M'[l]. grid (64,4), 128 thr (4 warps), l-tile 64.
// smem: kt 16KB | qt 32KB
// ---------------------------------------------------------------------------
__global__ __launch_bounds__(128) void stats_kernel()
{
    extern __shared__ char smc[];
    char* kt = smc;
    char* qt = smc + 16384;
    uint32_t ktb = smem_u32(kt), qtb = smem_u32(qt);

    int n = blockIdx.y, l0 = blockIdx.x * 64, t = threadIdx.x;
    int lane = t & 31, w = t >> 5;
    int lw = w * 16;

    const uint4* ksrc = (const uint4*)(g_kT + ((size_t)n * LL + l0) * CH);
#pragma unroll
    for (int i = t; i < 1024; i += 128) {
        int row = i >> 4, ch = i & 15;
        *(uint4*)(kt + sw_off(row, ch)) = ksrc[row * 16 + ch];
    }
    __syncthreads();

    uint32_t af[8][4];
#pragma unroll
    for (int kk = 0; kk < 8; kk++) ldsm_x4(a_addr(ktb, lw, kk, lane), af[kk]);

    const uint4* qsrc = (const uint4*)(g_qT + (size_t)n * LL * CH);

    float rM0 = -3.0e38f, rS0 = 0.f, rM1 = -3.0e38f, rS1 = 0.f;

    for (int mc = 0; mc < 32; mc++) {
        if (mc) __syncthreads();
#pragma unroll
        for (int i = t; i < 2048; i += 128) {
            int row = i >> 4, ch = i & 15;
            *(uint4*)(qt + sw_off(row, ch)) = qsrc[(mc * 128 + row) * 16 + ch];
        }
        __syncthreads();

        float sacc[16][4];
#pragma unroll
        for (int j = 0; j < 16; j++)
#pragma unroll
            for (int q = 0; q < 4; q++) sacc[j][q] = 0.f;

#pragma unroll
        for (int kk = 0; kk < 8; kk++) {
#pragma unroll
            for (int jp = 0; jp < 8; jp++) {
                uint32_t b[4];
                ldsm_x4(b_addr(qtb, jp * 16, kk, lane), b);
                mma_bf16(sacc[jp * 2],     af[kk], b);
                mma_bf16(sacc[jp * 2 + 1], af[kk], b + 2);
            }
        }

        float mx0 = -3.0e38f, mx1 = -3.0e38f;
#pragma unroll
        for (int j = 0; j < 16; j++) {
            mx0 = fmaxf(mx0, fmaxf(sacc[j][0], sacc[j][1]));
            mx1 = fmaxf(mx1, fmaxf(sacc[j][2], sacc[j][3]));
        }
        float nm0 = fmaxf(rM0, mx0);
        float nm1 = fmaxf(rM1, mx1);
        float s0 = 0.f, s1 = 0.f;
#pragma unroll
        for (int j = 0; j < 16; j++) {
            s0 += __expf(sacc[j][0] - nm0) + __expf(sacc[j][1] - nm0);
            s1 += __expf(sacc[j][2] - nm1) + __expf(sacc[j][3] - nm1);
        }
        rS0 = rS0 * __expf(rM0 - nm0) + s0; rM0 = nm0;
        rS1 = rS1 * __expf(rM1 - nm1) + s1; rM1 = nm1;
    }

#pragma unroll
    for (int d = 1; d < 4; d <<= 1) {
        float oM = __shfl_xor_sync(0xffffffffu, rM0, d);
        float oS = __shfl_xor_sync(0xffffffffu, rS0, d);
        float nm = fmaxf(rM0, oM);
        rS0 = rS0 * __expf(rM0 - nm) + oS * __expf(oM - nm);
        rM0 = nm;
        oM = __shfl_xor_sync(0xffffffffu, rM1, d);
        oS = __shfl_xor_sync(0xffffffffu, rS1, d);
        nm = fmaxf(rM1, oM);
        rS1 = rS1 * __expf(rM1 - nm) + oS * __expf(oM - nm);
        rM1 = nm;
    }
    if ((lane & 3) == 0) {
        int r = l0 + lw + (lane >> 2);
        g_mprime[n * LL + r]     = rM0 + __logf(rS0);
        g_mprime[n * LL + r + 8] = rM1 + __logf(rS1);
    }
}

// ---------------------------------------------------------------------------
// Kernel C: out[c,m] = x[c,m] + sum_l v[c,l]*exp(s[l,m]-M'[l]).
// grid (64,4), 128 thr (4 warps), m-tile 64 -> 2 CTAs/SM.
// smem: qt 16K | kt 32K | vt 32K | pt 16K | mp 512B  (96.5KB)
// ---------------------------------------------------------------------------
__global__ __launch_bounds__(128) void attn_kernel(
    const float* __restrict__ x, float* __restrict__ out)
{
    extern __shared__ char smc[];
    char* qt = smc;
    char* kt = smc + 16384;
    char* vt = smc + 49152;
    char* pt = smc + 81920;
    float* mp = (float*)(smc + 98304);
    uint32_t qtb = smem_u32(qt), ktb = smem_u32(kt);
    uint32_t vtb = smem_u32(vt), ptb = smem_u32(pt);

    int n = blockIdx.y, m0 = blockIdx.x * 64, t = threadIdx.x;
    int lane = t & 31, w = t >> 5;
    int lw = w * 16, rw2 = w * 32;
    int mrow = lw + (lane >> 2);
    int ecol = (lane & 3) * 2;

    const uint4* qsrc = (const uint4*)(g_qT + ((size_t)n * LL + m0) * CH);
#pragma unroll
    for (int i = t; i < 1024; i += 128) {
        int row = i >> 4, ch = i & 15;
        *(uint4*)(qt + sw_off(row, ch)) = qsrc[row * 16 + ch];
    }
    __syncthreads();

    uint32_t af[8][4];
#pragma unroll
    for (int kk = 0; kk < 8; kk++) ldsm_x4(a_addr(qtb, lw, kk, lane), af[kk]);

    const uint4* ksrc = (const uint4*)(g_kT + (size_t)n * LL * CH);
    const uint4* vsrc = (const uint4*)(g_vB + (size_t)n * CH * LL); // pitch 512 u4

    float oacc[16][4];
#pragma unroll
    for (int j = 0; j < 16; j++)
#pragma unroll
        for (int q = 0; q < 4; q++) oacc[j][q] = 0.f;

    for (int lc = 0; lc < 32; lc++) {
        __syncthreads();
#pragma unroll
        for (int i = t; i < 2048; i += 128) {
            int row = i >> 4, ch = i & 15;
            *(uint4*)(kt + sw_off(row, ch)) = ksrc[(lc * 128 + row) * 16 + ch];
            *(uint4*)(vt + sw_off(row, ch)) = vsrc[row * 512 + lc * 16 + ch];
        }
        mp[t] = g_mprime[n * LL + lc * 128 + t];
        __syncthreads();

        // S^T[m][l] for warp's 16 m-rows
        float sacc[16][4];
#pragma unroll
        for (int j = 0; j < 16; j++)
#pragma unroll
            for (int q = 0; q < 4; q++) sacc[j][q] = 0.f;
#pragma unroll
        for (int kk = 0; kk < 8; kk++) {
#pragma unroll
            for (int jp = 0; jp < 8; jp++) {
                uint32_t b[4];
                ldsm_x4(b_addr(ktb, jp * 16, kk, lane), b);
                mma_bf16(sacc[jp * 2],     af[kk], b);
                mma_bf16(sacc[jp * 2 + 1], af[kk], b + 2);
            }
        }

        // exp -> P^T [m][l] bf16
#pragma unroll
        for (int j = 0; j < 16; j++) {
            int l = j * 8 + ecol;
            float mp0 = mp[l], mp1 = mp[l + 1];
            uint32_t p01 = pk_bf16(__expf(sacc[j][0] - mp0),
                                   __expf(sacc[j][1] - mp1));
            uint32_t p23 = pk_bf16(__expf(sacc[j][2] - mp0),
                                   __expf(sacc[j][3] - mp1));
            *(uint32_t*)(pt + sw_off(mrow,     j) + ecol * 2) = p01;
            *(uint32_t*)(pt + sw_off(mrow + 8, j) + ecol * 2) = p23;
        }
        __syncthreads();

        // out[c][m] += v[c][l-chunk] * P[l-chunk][m]; warp owns 32 c-rows
#pragma unroll
        for (int kk = 0; kk < 8; kk++) {
            uint32_t a0[4], a1[4];
            ldsm_x4(a_addr(vtb, rw2,      kk, lane), a0);
            ldsm_x4(a_addr(vtb, rw2 + 16, kk, lane), a1);
#pragma unroll
            for (int bp = 0; bp < 4; bp++) {
                uint32_t b[4];
                ldsm_x4(b_addr(ptb, bp * 16, kk, lane), b);
                mma_bf16(oacc[bp * 2],         a0, b);
                mma_bf16(oacc[bp * 2 + 1],     a0, b + 2);
                mma_bf16(oacc[8 + bp * 2],     a1, b);
                mma_bf16(oacc[8 + bp * 2 + 1], a1, b + 2);
            }
        }
    }

    const float* xb = x + (size_t)n * CH * LL;
    float* ob = out + (size_t)n * CH * LL;
#pragma unroll
    for (int set = 0; set < 2; set++) {
        int c0 = rw2 + set * 16 + (lane >> 2);
#pragma unroll
        for (int j = 0; j < 8; j++) {
            size_t off0 = (size_t)c0 * LL + m0 + j * 8 + ecol;
            size_t off1 = (size_t)(c0 + 8) * LL + m0 + j * 8 + ecol;
            float2 x0 = *(const float2*)(xb + off0);
            float2 x1 = *(const float2*)(xb + off1);
            float2 r0 = make_float2(oacc[set * 8 + j][0] + x0.x,
                                    oacc[set * 8 + j][1] + x0.y);
            float2 r1 = make_float2(oacc[set * 8 + j][2] + x1.x,
                                    oacc[set * 8 + j][3] + x1.y);
            *(float2*)(ob + off0) = r0;
            *(float2*)(ob + off1) = r1;
        }
    }
}

// ---------------------------------------------------------------------------
extern "C" void kernel_launch(void* const* d_in, const int* in_sizes, int n_in,
                              void* d_out, int out_size)
{
    const float* x  = (const float*)d_in[0];
    const float* Wq = (const float*)d_in[1];
    const float* bq = (const float*)d_in[2];
    const float* Wk = (const float*)d_in[3];
    const float* bk = (const float*)d_in[4];
    const float* Wv = (const float*)d_in[5];
    const float* bv = (const float*)d_in[6];
    float* out = (float*)d_out;

    cudaFuncSetAttribute(qkv_kernel,   cudaFuncAttributeMaxDynamicSharedMemorySize, 49664);
    cudaFuncSetAttribute(stats_kernel, cudaFuncAttributeMaxDynamicSharedMemorySize, 49152);
    cudaFuncSetAttribute(attn_kernel,  cudaFuncAttributeMaxDynamicSharedMemorySize, 98816);

    xpose_kernel<<<dim3(128, 4), 256>>>(x);
    qkv_kernel<<<dim3(64, 4), 128, 49664>>>(Wq, bq, Wk, bk, Wv, bv);
    stats_kernel<<<dim3(64, 4), 128, 49152>>>();
    attn_kernel<<<dim3(64, 4), 128, 98816>>>(x, out);
}

// round 5
// speedup vs baseline: 5.7517x; 1.0864x over previous
#include <cuda_runtime.h>
#include <cuda_bf16.h>
#include <stdint.h>

#define NB 4
#define CH 128
#define LL 4096
// SCALE * log2(e): scores produced directly in log2 domain
#define SCALE_L2E ((float)(0.08838834764831845 * 1.4426950408889634))

// ---------------------------------------------------------------------------
// Scratch (allocation-free: static device globals)
// ---------------------------------------------------------------------------
__device__ __nv_bfloat16  g_xT[(size_t)NB * LL * CH];  // x^T [n][m][c]
__device__ __nv_bfloat16  g_qT[(size_t)NB * LL * CH];  // q^T [n][m][c]
__device__ __nv_bfloat16  g_kT[(size_t)NB * LL * CH];  // k^T [n][l][c], pre-scaled by SCALE*log2e
__device__ __nv_bfloat16  g_vB[(size_t)NB * CH * LL];  // v   [n][c][l]
__device__ float          g_mpA[NB * LL];              // m' for m-half 0 (log2 domain)
__device__ float          g_mpB[NB * LL];              // m' for m-half 1
__device__ float          g_part[2 * (size_t)NB * CH * LL]; // attn partials per l-half

// ---------------------------------------------------------------------------
// Helpers
// ---------------------------------------------------------------------------
__device__ __forceinline__ uint32_t smem_u32(const void* p) {
    uint32_t a;
    asm("{ .reg .u64 t; cvta.to.shared.u64 t, %1; cvt.u32.u64 %0, t; }"
        : "=r"(a) : "l"(p));
    return a;
}
__device__ __forceinline__ uint32_t pk_bf16(float a, float b) {
    __nv_bfloat162 t = __floats2bfloat162_rn(a, b);
    return *reinterpret_cast<uint32_t*>(&t);
}
__device__ __forceinline__ float fexp2(float x) {
    float y; asm("ex2.approx.f32 %0, %1;" : "=f"(y) : "f"(x)); return y;
}
__device__ __forceinline__ float flog2(float x) {
    float y; asm("lg2.approx.f32 %0, %1;" : "=f"(y) : "f"(x)); return y;
}

// Swizzled tile offset; pitch = bytes/row (256 for 128-bf16 rows, 128 for 64)
__device__ __forceinline__ uint32_t swz(int row, int ch, int pitch) {
    return (uint32_t)row * (uint32_t)pitch + (uint32_t)((ch ^ (row & 7)) << 4);
}
__device__ __forceinline__ void ldsm_x4(uint32_t addr, uint32_t* r) {
    asm volatile("ldmatrix.sync.aligned.m8n8.x4.shared.b16 {%0,%1,%2,%3}, [%4];"
        : "=r"(r[0]), "=r"(r[1]), "=r"(r[2]), "=r"(r[3]) : "r"(addr));
}
__device__ __forceinline__ uint32_t a_addr(uint32_t tb, int r0, int kk, int lane, int pitch) {
    return tb + swz(r0 + (lane & 15), kk * 2 + (lane >> 4), pitch);
}
__device__ __forceinline__ uint32_t b_addr(uint32_t tb, int n0, int kk, int lane, int pitch) {
    int g = lane >> 3;
    return tb + swz(n0 + (lane & 7) + ((g & 2) ? 8 : 0), kk * 2 + (g & 1), pitch);
}
__device__ __forceinline__ void mma_bf16(float* d, const uint32_t* a, const uint32_t* b) {
    asm volatile(
        "mma.sync.aligned.m16n8k16.row.col.f32.bf16.bf16.f32 "
        "{%0,%1,%2,%3}, {%4,%5,%6,%7}, {%8,%9}, {%0,%1,%2,%3};"
        : "+f"(d[0]), "+f"(d[1]), "+f"(d[2]), "+f"(d[3])
        : "r"(a[0]), "r"(a[1]), "r"(a[2]), "r"(a[3]), "r"(b[0]), "r"(b[1]));
}
__device__ __forceinline__ void cpa16(uint32_t dst, const void* src) {
    asm volatile("cp.async.cg.shared.global [%0], [%1], 16;" :: "r"(dst), "l"(src));
}
#define CPA_COMMIT() asm volatile("cp.async.commit_group;" ::: "memory")
#define CPA_WAIT(n)  asm volatile("cp.async.wait_group %0;" :: "n"(n) : "memory")

// ---------------------------------------------------------------------------
// Kernel 0: transpose+convert  x [n][c][m] fp32 -> g_xT [n][m][c] bf16
// ---------------------------------------------------------------------------
__global__ __launch_bounds__(256) void xpose_kernel(const float* __restrict__ x)
{
    __shared__ float ts[128][33];
    int n = blockIdx.y, m0 = blockIdx.x * 32, t = threadIdx.x;
    const float* xb = x + (size_t)n * CH * LL;
#pragma unroll
    for (int i = 0; i < 16; i++) {
        int c = i * 8 + (t >> 5);
        ts[c][t & 31] = xb[(size_t)c * LL + m0 + (t & 31)];
    }
    __syncthreads();
    int ml = t >> 3, cg = t & 7;
    __nv_bfloat16* dst = g_xT + ((size_t)n * LL + m0 + ml) * CH + cg * 16;
#pragma unroll
    for (int u = 0; u < 2; u++) {
        int cb = cg * 16 + u * 8;
        uint4 o;
        o.x = pk_bf16(ts[cb + 0][ml], ts[cb + 1][ml]);
        o.y = pk_bf16(ts[cb + 2][ml], ts[cb + 3][ml]);
        o.z = pk_bf16(ts[cb + 4][ml], ts[cb + 5][ml]);
        o.w = pk_bf16(ts[cb + 6][ml], ts[cb + 7][ml]);
        *(uint4*)(dst + u * 8) = o;
    }
}

// ---------------------------------------------------------------------------
// Kernel A: q/k/v via HMMA.  grid (64,4), 128 thr.
// ---------------------------------------------------------------------------
__global__ __launch_bounds__(128) void qkv_kernel(
    const float* __restrict__ Wq, const float* __restrict__ bq,
    const float* __restrict__ Wk, const float* __restrict__ bk,
    const float* __restrict__ Wv, const float* __restrict__ bv)
{
    extern __shared__ char smc[];
    char* xt = smc;
    char* wt = smc + 16384;
    float* bias = (float*)(smc + 49152);
    uint32_t xtb = smem_u32(xt), wtb = smem_u32(wt);
    int n = blockIdx.y, m0 = blockIdx.x * 64, t = threadIdx.x;
    int lane = t & 31, w = t >> 5;
    int ecol = (lane & 3) * 2;

    const uint4* xsrc = (const uint4*)(g_xT + ((size_t)n * LL + m0) * CH);
#pragma unroll
    for (int i = t; i < 1024; i += 128) {
        int row = i >> 4, ch = i & 15;
        *(uint4*)(xt + swz(row, ch, 256)) = xsrc[row * 16 + ch];
    }

    const float* Wm[3] = {Wq, Wk, Wv};
    const float* Bv[3] = {bq, bk, bv};

    for (int wi = 0; wi < 3; wi++) {
        __syncthreads();
#pragma unroll
        for (int i = t; i < 2048; i += 128) {
            int row = i >> 4, ch = i & 15;
            const float* src = Wm[wi] + row * 128 + ch * 8;
            float4 f0 = *(const float4*)src;
            float4 f1 = *(const float4*)(src + 4);
            uint4 u;
            u.x = pk_bf16(f0.x, f0.y); u.y = pk_bf16(f0.z, f0.w);
            u.z = pk_bf16(f1.x, f1.y); u.w = pk_bf16(f1.z, f1.w);
            *(uint4*)(wt + swz(row, ch, 256)) = u;
        }
        bias[t] = Bv[wi][t];
        __syncthreads();

        if (wi < 2) {
            int lw = w * 16;
            float sacc[16][4];
#pragma unroll
            for (int j = 0; j < 16; j++)
#pragma unroll
                for (int q = 0; q < 4; q++) sacc[j][q] = 0.f;
#pragma unroll
            for (int kk = 0; kk < 8; kk++) {
                uint32_t a[4];
                ldsm_x4(a_addr(xtb, lw, kk, lane, 256), a);
#pragma unroll
                for (int jp = 0; jp < 8; jp++) {
                    uint32_t b[4];
                    ldsm_x4(b_addr(wtb, jp * 16, kk, lane, 256), b);
                    mma_bf16(sacc[jp * 2],     a, b);
                    mma_bf16(sacc[jp * 2 + 1], a, b + 2);
                }
            }
            int mrow = m0 + lw + (lane >> 2);
            __nv_bfloat16* dst = (wi == 0 ? g_qT : g_kT) + (size_t)n * LL * CH;
            float sc = (wi == 0) ? 1.0f : SCALE_L2E;
#pragma unroll
            for (int j = 0; j < 16; j++) {
                int o = (j >> 1) * 16 + (j & 1) * 8 + ecol;
                float b0 = bias[o], b1 = bias[o + 1];
                *(uint32_t*)(dst + (size_t)mrow * CH + o) =
                    pk_bf16((sacc[j][0] + b0) * sc, (sacc[j][1] + b1) * sc);
                *(uint32_t*)(dst + (size_t)(mrow + 8) * CH + o) =
                    pk_bf16((sacc[j][2] + b0) * sc, (sacc[j][3] + b1) * sc);
            }
        } else {
            int rw2 = w * 32;
            float vacc[16][4];
#pragma unroll
            for (int j = 0; j < 16; j++)
#pragma unroll
                for (int q = 0; q < 4; q++) vacc[j][q] = 0.f;
#pragma unroll
            for (int kk = 0; kk < 8; kk++) {
                uint32_t a0[4], a1[4];
                ldsm_x4(a_addr(wtb, rw2,      kk, lane, 256), a0);
                ldsm_x4(a_addr(wtb, rw2 + 16, kk, lane, 256), a1);
#pragma unroll
                for (int bp = 0; bp < 4; bp++) {
                    uint32_t b[4];
                    ldsm_x4(b_addr(xtb, bp * 16, kk, lane, 256), b);
                    mma_bf16(vacc[bp * 2],         a0, b);
                    mma_bf16(vacc[bp * 2 + 1],     a0, b + 2);
                    mma_bf16(vacc[8 + bp * 2],     a1, b);
                    mma_bf16(vacc[8 + bp * 2 + 1], a1, b + 2);
                }
            }
#pragma unroll
            for (int set = 0; set < 2; set++) {
                int o = rw2 + set * 16 + (lane >> 2);
                float bo0 = bias[o], bo1 = bias[o + 8];
#pragma unroll
                for (int j = 0; j < 8; j++) {
                    int mc = m0 + j * 8 + ecol;
                    *(uint32_t*)(g_vB + ((size_t)n * CH + o) * LL + mc) =
                        pk_bf16(vacc[set * 8 + j][0] + bo0, vacc[set * 8 + j][1] + bo0);
                    *(uint32_t*)(g_vB + ((size_t)n * CH + o + 8) * LL + mc) =
                        pk_bf16(vacc[set * 8 + j][2] + bo1, vacc[set * 8 + j][3] + bo1);
                }
            }
        }
    }
}

// ---------------------------------------------------------------------------
// Kernel B: per-(l, m-half) stats in log2 domain.
// grid (64, 4, 2), 128 thr. smem: kt 16K | qt db 2x16K  (48K, 4 CTA/SM)
// ---------------------------------------------------------------------------
__global__ __launch_bounds__(128, 4) void stats_kernel()
{
    extern __shared__ char smc[];
    char* kt = smc;
    char* qt0 = smc + 16384;
    char* qt1 = smc + 32768;
    uint32_t ktb = smem_u32(kt);
    uint32_t qtb[2] = {smem_u32(qt0), smem_u32(qt1)};

    int n = blockIdx.y, l0 = blockIdx.x * 64, t = threadIdx.x;
    int mh = blockIdx.z;
    int mbase = mh * 2048;
    int lane = t & 31, w = t >> 5;
    int lw = w * 16;

    // persistent kt (regular loads)
    const uint4* ksrc = (const uint4*)(g_kT + ((size_t)n * LL + l0) * CH);
#pragma unroll
    for (int i = t; i < 1024; i += 128) {
        int row = i >> 4, ch = i & 15;
        *(uint4*)(kt + swz(row, ch, 256)) = ksrc[row * 16 + ch];
    }

    const uint4* qsrc = (const uint4*)(g_qT + (size_t)n * LL * CH);
    // prefetch qt chunk 0
#pragma unroll
    for (int i = t; i < 1024; i += 128) {
        int row = i >> 4, ch = i & 15;
        cpa16(qtb[0] + swz(row, ch, 256), &qsrc[(mbase + row) * 16 + ch]);
    }
    CPA_COMMIT();
    __syncthreads();

    uint32_t af[8][4];
#pragma unroll
    for (int kk = 0; kk < 8; kk++) ldsm_x4(a_addr(ktb, lw, kk, lane, 256), af[kk]);

    float rM = -3.0e38f, rS = 0.f;      // row lw + lane>>2
    float rM1 = -3.0e38f, rS1 = 0.f;    // row +8

    for (int mc = 0; mc < 32; mc++) {
        __syncthreads();   // everyone done with qt[(mc+1)&1] from iter mc-1
        if (mc < 31) {
            int mb = mbase + (mc + 1) * 64;
#pragma unroll
            for (int i = t; i < 1024; i += 128) {
                int row = i >> 4, ch = i & 15;
                cpa16(qtb[(mc + 1) & 1] + swz(row, ch, 256), &qsrc[(mb + row) * 16 + ch]);
            }
        }
        CPA_COMMIT();
        CPA_WAIT(1);       // qt(mc) ready
        __syncthreads();

        uint32_t qb = qtb[mc & 1];
        float sacc[8][4];
#pragma unroll
        for (int j = 0; j < 8; j++)
#pragma unroll
            for (int q = 0; q < 4; q++) sacc[j][q] = 0.f;
#pragma unroll
        for (int kk = 0; kk < 8; kk++) {
#pragma unroll
            for (int jp = 0; jp < 4; jp++) {
                uint32_t b[4];
                ldsm_x4(b_addr(qb, jp * 16, kk, lane, 256), b);
                mma_bf16(sacc[jp * 2],     af[kk], b);
                mma_bf16(sacc[jp * 2 + 1], af[kk], b + 2);
            }
        }
        float mx0 = -3.0e38f, mx1 = -3.0e38f;
#pragma unroll
        for (int j = 0; j < 8; j++) {
            mx0 = fmaxf(mx0, fmaxf(sacc[j][0], sacc[j][1]));
            mx1 = fmaxf(mx1, fmaxf(sacc[j][2], sacc[j][3]));
        }
        float nm0 = fmaxf(rM, mx0), nm1 = fmaxf(rM1, mx1);
        float s0 = 0.f, s1 = 0.f;
#pragma unroll
        for (int j = 0; j < 8; j++) {
            s0 += fexp2(sacc[j][0] - nm0) + fexp2(sacc[j][1] - nm0);
            s1 += fexp2(sacc[j][2] - nm1) + fexp2(sacc[j][3] - nm1);
        }
        rS  = rS  * fexp2(rM  - nm0) + s0; rM  = nm0;
        rS1 = rS1 * fexp2(rM1 - nm1) + s1; rM1 = nm1;
    }

#pragma unroll
    for (int d = 1; d < 4; d <<= 1) {
        float oM = __shfl_xor_sync(0xffffffffu, rM, d);
        float oS = __shfl_xor_sync(0xffffffffu, rS, d);
        float nm = fmaxf(rM, oM);
        rS = rS * fexp2(rM - nm) + oS * fexp2(oM - nm);
        rM = nm;
        oM = __shfl_xor_sync(0xffffffffu, rM1, d);
        oS = __shfl_xor_sync(0xffffffffu, rS1, d);
        nm = fmaxf(rM1, oM);
        rS1 = rS1 * fexp2(rM1 - nm) + oS * fexp2(oM - nm);
        rM1 = nm;
    }
    if ((lane & 3) == 0) {
        int r = n * LL + l0 + lw + (lane >> 2);
        float* dst = mh ? g_mpB : g_mpA;
        dst[r]     = rM  + flog2(rS);
        dst[r + 8] = rM1 + flog2(rS1);
    }
}

// ---------------------------------------------------------------------------
// Kernel C: partial attn over one l-half.
// grid (64, 4, 2), 128 thr, launch_bounds(128,3).
// smem: qt 16K | kt db 2x16K | vt 16K | pt 8K | mp 256B  (73984 B, 3 CTA/SM)
// ---------------------------------------------------------------------------
__global__ __launch_bounds__(128, 3) void attn_kernel()
{
    extern __shared__ char smc[];
    char* qt  = smc;
    char* kt0 = smc + 16384;
    char* kt1 = smc + 32768;
    char* vt  = smc + 49152;
    char* pt  = smc + 65536;
    float* mp = (float*)(smc + 73728);
    uint32_t qtb = smem_u32(qt);
    uint32_t ktb[2] = {smem_u32(kt0), smem_u32(kt1)};
    uint32_t vtb = smem_u32(vt), ptb = smem_u32(pt);

    int n = blockIdx.y, m0 = blockIdx.x * 64, t = threadIdx.x;
    int lh = blockIdx.z;
    int lbase = lh * 2048;
    int lane = t & 31, w = t >> 5;
    int lw = w * 16, rw2 = w * 32;
    int mrow = lw + (lane >> 2);
    int ecol = (lane & 3) * 2;

    // persistent qt (regular loads)
    const uint4* qsrc = (const uint4*)(g_qT + ((size_t)n * LL + m0) * CH);
#pragma unroll
    for (int i = t; i < 1024; i += 128) {
        int row = i >> 4, ch = i & 15;
        *(uint4*)(qt + swz(row, ch, 256)) = qsrc[row * 16 + ch];
    }

    const uint4* ksrc = (const uint4*)(g_kT + (size_t)n * LL * CH);
    const uint4* vsrc = (const uint4*)(g_vB + (size_t)n * CH * LL); // pitch 512 u4

    // prefetch kt chunk 0
#pragma unroll
    for (int i = t; i < 1024; i += 128) {
        int row = i >> 4, ch = i & 15;
        cpa16(ktb[0] + swz(row, ch, 256), &ksrc[(lbase + row) * 16 + ch]);
    }
    CPA_COMMIT();

    float oacc[16][4];
#pragma unroll
    for (int j = 0; j < 16; j++)
#pragma unroll
        for (int q = 0; q < 4; q++) oacc[j][q] = 0.f;

    for (int lc = 0; lc < 32; lc++) {
        __syncthreads();   // prior mma1/mma2 reads of kt[(lc+1)&1], vt, pt done
        int lcur = lbase + lc * 64;
        // vt(lc): overlaps with mma1+exp below
#pragma unroll
        for (int i = t; i < 1024; i += 128) {
            int row = i >> 3, ch = i & 7;
            cpa16(vtb + swz(row, ch, 128), &vsrc[row * 512 + (lcur >> 3) + ch]);
        }
        CPA_COMMIT();
        // kt(lc+1): overlaps with whole iteration
        if (lc < 31) {
            int lnext = lcur + 64;
#pragma unroll
            for (int i = t; i < 1024; i += 128) {
                int row = i >> 4, ch = i & 15;
                cpa16(ktb[(lc + 1) & 1] + swz(row, ch, 256), &ksrc[(lnext + row) * 16 + ch]);
            }
        }
        CPA_COMMIT();
        if (t < 64) {
            int gl = n * LL + lcur + t;
            float a = g_mpA[gl], b = g_mpB[gl];
            float mx = fmaxf(a, b), mn = fminf(a, b);
            mp[t] = mx + flog2(1.0f + fexp2(mn - mx));
        }
        CPA_WAIT(2);       // kt(lc) ready
        __syncthreads();

        // mma1: S^T[m 16][l 64] = qt x kt
        uint32_t kb = ktb[lc & 1];
        float sacc[8][4];
#pragma unroll
        for (int j = 0; j < 8; j++)
#pragma unroll
            for (int q = 0; q < 4; q++) sacc[j][q] = 0.f;
#pragma unroll
        for (int kk = 0; kk < 8; kk++) {
            uint32_t a[4];
            ldsm_x4(a_addr(qtb, lw, kk, lane, 256), a);
#pragma unroll
            for (int jp = 0; jp < 4; jp++) {
                uint32_t b[4];
                ldsm_x4(b_addr(kb, jp * 16, kk, lane, 256), b);
                mma_bf16(sacc[jp * 2],     a, b);
                mma_bf16(sacc[jp * 2 + 1], a, b + 2);
            }
        }
        // exp -> pt (P^T [m 64][l 64] bf16, pitch 128)
#pragma unroll
        for (int j = 0; j < 8; j++) {
            int l = j * 8 + ecol;
            float mp0 = mp[l], mp1 = mp[l + 1];
            uint32_t p01 = pk_bf16(fexp2(sacc[j][0] - mp0), fexp2(sacc[j][1] - mp1));
            uint32_t p23 = pk_bf16(fexp2(sacc[j][2] - mp0), fexp2(sacc[j][3] - mp1));
            *(uint32_t*)(pt + swz(mrow,     j, 128) + ecol * 2) = p01;
            *(uint32_t*)(pt + swz(mrow + 8, j, 128) + ecol * 2) = p23;
        }
        CPA_WAIT(1);       // vt(lc) ready (kt(lc+1) may still fly)
        __syncthreads();

        // mma2: out[c 32][m 64] += v[c][l] * P[l][m]
#pragma unroll
        for (int kk = 0; kk < 4; kk++) {
            uint32_t a0[4], a1[4];
            ldsm_x4(a_addr(vtb, rw2,      kk, lane, 128), a0);
            ldsm_x4(a_addr(vtb, rw2 + 16, kk, lane, 128), a1);
#pragma unroll
            for (int bp = 0; bp < 4; bp++) {
                uint32_t b[4];
                ldsm_x4(b_addr(ptb, bp * 16, kk, lane, 128), b);
                mma_bf16(oacc[bp * 2],         a0, b);
                mma_bf16(oacc[bp * 2 + 1],     a0, b + 2);
                mma_bf16(oacc[8 + bp * 2],     a1, b);
                mma_bf16(oacc[8 + bp * 2 + 1], a1, b + 2);
            }
        }
    }

    // write partial
    float* pb = g_part + (size_t)lh * NB * CH * LL + (size_t)n * CH * LL;
#pragma unroll
    for (int set = 0; set < 2; set++) {
        int c0 = rw2 + set * 16 + (lane >> 2);
#pragma unroll
        for (int j = 0; j < 8; j++) {
            size_t off0 = (size_t)c0 * LL + m0 + j * 8 + ecol;
            size_t off1 = (size_t)(c0 + 8) * LL + m0 + j * 8 + ecol;
            *(float2*)(pb + off0) = make_float2(oacc[set * 8 + j][0], oacc[set * 8 + j][1]);
            *(float2*)(pb + off1) = make_float2(oacc[set * 8 + j][2], oacc[set * 8 + j][3]);
        }
    }
}

// ---------------------------------------------------------------------------
// Kernel D: out = x + part0 + part1
// ---------------------------------------------------------------------------
__global__ __launch_bounds__(256) void combine_kernel(
    const float* __restrict__ x, float* __restrict__ out)
{
    size_t i = ((size_t)blockIdx.x * 256 + threadIdx.x) * 4;
    float4 a = *(const float4*)(x + i);
    float4 b = *(const float4*)(g_part + i);
    float4 c = *(const float4*)(g_part + (size_t)NB * CH * LL + i);
    a.x += b.x + c.x; a.y += b.y + c.y; a.z += b.z + c.z; a.w += b.w + c.w;
    *(float4*)(out + i) = a;
}

// ---------------------------------------------------------------------------
extern "C" void kernel_launch(void* const* d_in, const int* in_sizes, int n_in,
                              void* d_out, int out_size)
{
    const float* x  = (const float*)d_in[0];
    const float* Wq = (const float*)d_in[1];
    const float* bq = (const float*)d_in[2];
    const float* Wk = (const float*)d_in[3];
    const float* bk = (const float*)d_in[4];
    const float* Wv = (const float*)d_in[5];
    const float* bv = (const float*)d_in[6];
    float* out = (float*)d_out;

    cudaFuncSetAttribute(qkv_kernel,   cudaFuncAttributeMaxDynamicSharedMemorySize, 49664);
    cudaFuncSetAttribute(stats_kernel, cudaFuncAttributeMaxDynamicSharedMemorySize, 49152);
    cudaFuncSetAttribute(attn_kernel,  cudaFuncAttributeMaxDynamicSharedMemorySize, 73984);

    xpose_kernel<<<dim3(128, 4), 256>>>(x);
    qkv_kernel<<<dim3(64, 4), 128, 49664>>>(Wq, bq, Wk, bk, Wv, bv);
    stats_kernel<<<dim3(64, 4, 2), 128, 49152>>>();
    attn_kernel<<<dim3(64, 4, 2), 128, 73984>>>();
    combine_kernel<<<(NB * CH * LL) / 1024, 256>>>(x, out);
}

// round 6
// speedup vs baseline: 6.2951x; 1.0945x over previous
#include <cuda_runtime.h>
#include <cuda_bf16.h>
#include <stdint.h>

#define NB 4
#define CH 128
#define LL 4096
// SCALE * log2(e): scores produced directly in log2 domain
#define SCALE_L2E ((float)(0.08838834764831845 * 1.4426950408889634))

// ---------------------------------------------------------------------------
// Scratch (allocation-free: static device globals)
// ---------------------------------------------------------------------------
__device__ __nv_bfloat16  g_xT[(size_t)NB * LL * CH];  // x^T [n][m][c]
__device__ __nv_bfloat16  g_qT[(size_t)NB * LL * CH];  // q^T [n][m][c]
__device__ __nv_bfloat16  g_kT[(size_t)NB * LL * CH];  // k^T [n][l][c], pre-scaled by SCALE*log2e
__device__ __nv_bfloat16  g_vB[(size_t)NB * CH * LL];  // v   [n][c][l]
__device__ float          g_mpA[NB * LL];              // m' for m-half 0 (log2 domain)
__device__ float          g_mpB[NB * LL];              // m' for m-half 1
__device__ float          g_part[2 * (size_t)NB * CH * LL]; // attn partials per l-half

// ---------------------------------------------------------------------------
// Helpers
// ---------------------------------------------------------------------------
__device__ __forceinline__ uint32_t smem_u32(const void* p) {
    uint32_t a;
    asm("{ .reg .u64 t; cvta.to.shared.u64 t, %1; cvt.u32.u64 %0, t; }"
        : "=r"(a) : "l"(p));
    return a;
}
__device__ __forceinline__ uint32_t pk_bf16(float a, float b) {
    __nv_bfloat162 t = __floats2bfloat162_rn(a, b);
    return *reinterpret_cast<uint32_t*>(&t);
}
__device__ __forceinline__ float fexp2(float x) {
    float y; asm("ex2.approx.f32 %0, %1;" : "=f"(y) : "f"(x)); return y;
}
__device__ __forceinline__ float flog2(float x) {
    float y; asm("lg2.approx.f32 %0, %1;" : "=f"(y) : "f"(x)); return y;
}

// Swizzled tile offset; pitch = bytes/row (256 for 128-bf16 rows, 128 for 64)
__device__ __forceinline__ uint32_t swz(int row, int ch, int pitch) {
    return (uint32_t)row * (uint32_t)pitch + (uint32_t)((ch ^ (row & 7)) << 4);
}
__device__ __forceinline__ void ldsm_x4(uint32_t addr, uint32_t* r) {
    asm volatile("ldmatrix.sync.aligned.m8n8.x4.shared.b16 {%0,%1,%2,%3}, [%4];"
        : "=r"(r[0]), "=r"(r[1]), "=r"(r[2]), "=r"(r[3]) : "r"(addr));
}
__device__ __forceinline__ uint32_t a_addr(uint32_t tb, int r0, int kk, int lane, int pitch) {
    return tb + swz(r0 + (lane & 15), kk * 2 + (lane >> 4), pitch);
}
__device__ __forceinline__ uint32_t b_addr(uint32_t tb, int n0, int kk, int lane, int pitch) {
    int g = lane >> 3;
    return tb + swz(n0 + (lane & 7) + ((g & 2) ? 8 : 0), kk * 2 + (g & 1), pitch);
}
__device__ __forceinline__ void mma_bf16(float* d, const uint32_t* a, const uint32_t* b) {
    asm volatile(
        "mma.sync.aligned.m16n8k16.row.col.f32.bf16.bf16.f32 "
        "{%0,%1,%2,%3}, {%4,%5,%6,%7}, {%8,%9}, {%0,%1,%2,%3};"
        : "+f"(d[0]), "+f"(d[1]), "+f"(d[2]), "+f"(d[3])
        : "r"(a[0]), "r"(a[1]), "r"(a[2]), "r"(a[3]), "r"(b[0]), "r"(b[1]));
}
__device__ __forceinline__ void cpa16(uint32_t dst, const void* src) {
    asm volatile("cp.async.cg.shared.global [%0], [%1], 16;" :: "r"(dst), "l"(src));
}
#define CPA_COMMIT() asm volatile("cp.async.commit_group;" ::: "memory")
#define CPA_WAIT(n)  asm volatile("cp.async.wait_group %0;" :: "n"(n) : "memory")

// ---------------------------------------------------------------------------
// Kernel 0: transpose+convert  x [n][c][m] fp32 -> g_xT [n][m][c] bf16
// ---------------------------------------------------------------------------
__global__ __launch_bounds__(256) void xpose_kernel(const float* __restrict__ x)
{
    __shared__ float ts[128][33];
    int n = blockIdx.y, m0 = blockIdx.x * 32, t = threadIdx.x;
    const float* xb = x + (size_t)n * CH * LL;
#pragma unroll
    for (int i = 0; i < 16; i++) {
        int c = i * 8 + (t >> 5);
        ts[c][t & 31] = xb[(size_t)c * LL + m0 + (t & 31)];
    }
    __syncthreads();
    int ml = t >> 3, cg = t & 7;
    __nv_bfloat16* dst = g_xT + ((size_t)n * LL + m0 + ml) * CH + cg * 16;
#pragma unroll
    for (int u = 0; u < 2; u++) {
        int cb = cg * 16 + u * 8;
        uint4 o;
        o.x = pk_bf16(ts[cb + 0][ml], ts[cb + 1][ml]);
        o.y = pk_bf16(ts[cb + 2][ml], ts[cb + 3][ml]);
        o.z = pk_bf16(ts[cb + 4][ml], ts[cb + 5][ml]);
        o.w = pk_bf16(ts[cb + 6][ml], ts[cb + 7][ml]);
        *(uint4*)(dst + u * 8) = o;
    }
}

// ---------------------------------------------------------------------------
// Kernel A: q/k/v via HMMA.  grid (64,4), 128 thr.
// ---------------------------------------------------------------------------
__global__ __launch_bounds__(128) void qkv_kernel(
    const float* __restrict__ Wq, const float* __restrict__ bq,
    const float* __restrict__ Wk, const float* __restrict__ bk,
    const float* __restrict__ Wv, const float* __restrict__ bv)
{
    extern __shared__ char smc[];
    char* xt = smc;
    char* wt = smc + 16384;
    float* bias = (float*)(smc + 49152);
    uint32_t xtb = smem_u32(xt), wtb = smem_u32(wt);
    int n = blockIdx.y, m0 = blockIdx.x * 64, t = threadIdx.x;
    int lane = t & 31, w = t >> 5;
    int ecol = (lane & 3) * 2;

    const uint4* xsrc = (const uint4*)(g_xT + ((size_t)n * LL + m0) * CH);
#pragma unroll
    for (int i = t; i < 1024; i += 128) {
        int row = i >> 4, ch = i & 15;
        *(uint4*)(xt + swz(row, ch, 256)) = xsrc[row * 16 + ch];
    }

    const float* Wm[3] = {Wq, Wk, Wv};
    const float* Bv[3] = {bq, bk, bv};

    for (int wi = 0; wi < 3; wi++) {
        __syncthreads();
#pragma unroll
        for (int i = t; i < 2048; i += 128) {
            int row = i >> 4, ch = i & 15;
            const float* src = Wm[wi] + row * 128 + ch * 8;
            float4 f0 = *(const float4*)src;
            float4 f1 = *(const float4*)(src + 4);
            uint4 u;
            u.x = pk_bf16(f0.x, f0.y); u.y = pk_bf16(f0.z, f0.w);
            u.z = pk_bf16(f1.x, f1.y); u.w = pk_bf16(f1.z, f1.w);
            *(uint4*)(wt + swz(row, ch, 256)) = u;
        }
        bias[t] = Bv[wi][t];
        __syncthreads();

        if (wi < 2) {
            int lw = w * 16;
            float sacc[16][4];
#pragma unroll
            for (int j = 0; j < 16; j++)
#pragma unroll
                for (int q = 0; q < 4; q++) sacc[j][q] = 0.f;
#pragma unroll
            for (int kk = 0; kk < 8; kk++) {
                uint32_t a[4];
                ldsm_x4(a_addr(xtb, lw, kk, lane, 256), a);
#pragma unroll
                for (int jp = 0; jp < 8; jp++) {
                    uint32_t b[4];
                    ldsm_x4(b_addr(wtb, jp * 16, kk, lane, 256), b);
                    mma_bf16(sacc[jp * 2],     a, b);
                    mma_bf16(sacc[jp * 2 + 1], a, b + 2);
                }
            }
            int mrow = m0 + lw + (lane >> 2);
            __nv_bfloat16* dst = (wi == 0 ? g_qT : g_kT) + (size_t)n * LL * CH;
            float sc = (wi == 0) ? 1.0f : SCALE_L2E;
#pragma unroll
            for (int j = 0; j < 16; j++) {
                int o = (j >> 1) * 16 + (j & 1) * 8 + ecol;
                float b0 = bias[o], b1 = bias[o + 1];
                *(uint32_t*)(dst + (size_t)mrow * CH + o) =
                    pk_bf16((sacc[j][0] + b0) * sc, (sacc[j][1] + b1) * sc);
                *(uint32_t*)(dst + (size_t)(mrow + 8) * CH + o) =
                    pk_bf16((sacc[j][2] + b0) * sc, (sacc[j][3] + b1) * sc);
            }
        } else {
            int rw2 = w * 32;
            float vacc[16][4];
#pragma unroll
            for (int j = 0; j < 16; j++)
#pragma unroll
                for (int q = 0; q < 4; q++) vacc[j][q] = 0.f;
#pragma unroll
            for (int kk = 0; kk < 8; kk++) {
                uint32_t a0[4], a1[4];
                ldsm_x4(a_addr(wtb, rw2,      kk, lane, 256), a0);
                ldsm_x4(a_addr(wtb, rw2 + 16, kk, lane, 256), a1);
#pragma unroll
                for (int bp = 0; bp < 4; bp++) {
                    uint32_t b[4];
                    ldsm_x4(b_addr(xtb, bp * 16, kk, lane, 256), b);
                    mma_bf16(vacc[bp * 2],         a0, b);
                    mma_bf16(vacc[bp * 2 + 1],     a0, b + 2);
                    mma_bf16(vacc[8 + bp * 2],     a1, b);
                    mma_bf16(vacc[8 + bp * 2 + 1], a1, b + 2);
                }
            }
#pragma unroll
            for (int set = 0; set < 2; set++) {
                int o = rw2 + set * 16 + (lane >> 2);
                float bo0 = bias[o], bo1 = bias[o + 8];
#pragma unroll
                for (int j = 0; j < 8; j++) {
                    int mc = m0 + j * 8 + ecol;
                    *(uint32_t*)(g_vB + ((size_t)n * CH + o) * LL + mc) =
                        pk_bf16(vacc[set * 8 + j][0] + bo0, vacc[set * 8 + j][1] + bo0);
                    *(uint32_t*)(g_vB + ((size_t)n * CH + o + 8) * LL + mc) =
                        pk_bf16(vacc[set * 8 + j][2] + bo1, vacc[set * 8 + j][3] + bo1);
                }
            }
        }
    }
}

// ---------------------------------------------------------------------------
// Kernel B: per-(l, m-half) stats in log2 domain.
// grid (64, 4, 2), 128 thr. smem: kt 16K | qt db 2x16K  (48K, 4 CTA/SM)
// ---------------------------------------------------------------------------
__global__ __launch_bounds__(128, 4) void stats_kernel()
{
    extern __shared__ char smc[];
    char* kt = smc;
    char* qt0 = smc + 16384;
    char* qt1 = smc + 32768;
    uint32_t ktb = smem_u32(kt);
    uint32_t qtb[2] = {smem_u32(qt0), smem_u32(qt1)};

    int n = blockIdx.y, l0 = blockIdx.x * 64, t = threadIdx.x;
    int mh = blockIdx.z;
    int mbase = mh * 2048;
    int lane = t & 31, w = t >> 5;
    int lw = w * 16;

    const uint4* ksrc = (const uint4*)(g_kT + ((size_t)n * LL + l0) * CH);
#pragma unroll
    for (int i = t; i < 1024; i += 128) {
        int row = i >> 4, ch = i & 15;
        *(uint4*)(kt + swz(row, ch, 256)) = ksrc[row * 16 + ch];
    }

    const uint4* qsrc = (const uint4*)(g_qT + (size_t)n * LL * CH);
#pragma unroll
    for (int i = t; i < 1024; i += 128) {
        int row = i >> 4, ch = i & 15;
        cpa16(qtb[0] + swz(row, ch, 256), &qsrc[(mbase + row) * 16 + ch]);
    }
    CPA_COMMIT();
    __syncthreads();

    uint32_t af[8][4];
#pragma unroll
    for (int kk = 0; kk < 8; kk++) ldsm_x4(a_addr(ktb, lw, kk, lane, 256), af[kk]);

    float rM = -3.0e38f, rS = 0.f;
    float rM1 = -3.0e38f, rS1 = 0.f;

    for (int mc = 0; mc < 32; mc++) {
        __syncthreads();
        if (mc < 31) {
            int mb = mbase + (mc + 1) * 64;
#pragma unroll
            for (int i = t; i < 1024; i += 128) {
                int row = i >> 4, ch = i & 15;
                cpa16(qtb[(mc + 1) & 1] + swz(row, ch, 256), &qsrc[(mb + row) * 16 + ch]);
            }
        }
        CPA_COMMIT();
        CPA_WAIT(1);
        __syncthreads();

        uint32_t qb = qtb[mc & 1];
        float sacc[8][4];
#pragma unroll
        for (int j = 0; j < 8; j++)
#pragma unroll
            for (int q = 0; q < 4; q++) sacc[j][q] = 0.f;
#pragma unroll
        for (int kk = 0; kk < 8; kk++) {
#pragma unroll
            for (int jp = 0; jp < 4; jp++) {
                uint32_t b[4];
                ldsm_x4(b_addr(qb, jp * 16, kk, lane, 256), b);
                mma_bf16(sacc[jp * 2],     af[kk], b);
                mma_bf16(sacc[jp * 2 + 1], af[kk], b + 2);
            }
        }
        float mx0 = -3.0e38f, mx1 = -3.0e38f;
#pragma unroll
        for (int j = 0; j < 8; j++) {
            mx0 = fmaxf(mx0, fmaxf(sacc[j][0], sacc[j][1]));
            mx1 = fmaxf(mx1, fmaxf(sacc[j][2], sacc[j][3]));
        }
        float nm0 = fmaxf(rM, mx0), nm1 = fmaxf(rM1, mx1);
        float s0 = 0.f, s1 = 0.f;
#pragma unroll
        for (int j = 0; j < 8; j++) {
            s0 += fexp2(sacc[j][0] - nm0) + fexp2(sacc[j][1] - nm0);
            s1 += fexp2(sacc[j][2] - nm1) + fexp2(sacc[j][3] - nm1);
        }
        rS  = rS  * fexp2(rM  - nm0) + s0; rM  = nm0;
        rS1 = rS1 * fexp2(rM1 - nm1) + s1; rM1 = nm1;
    }

#pragma unroll
    for (int d = 1; d < 4; d <<= 1) {
        float oM = __shfl_xor_sync(0xffffffffu, rM, d);
        float oS = __shfl_xor_sync(0xffffffffu, rS, d);
        float nm = fmaxf(rM, oM);
        rS = rS * fexp2(rM - nm) + oS * fexp2(oM - nm);
        rM = nm;
        oM = __shfl_xor_sync(0xffffffffu, rM1, d);
        oS = __shfl_xor_sync(0xffffffffu, rS1, d);
        nm = fmaxf(rM1, oM);
        rS1 = rS1 * fexp2(rM1 - nm) + oS * fexp2(oM - nm);
        rM1 = nm;
    }
    if ((lane & 3) == 0) {
        int r = n * LL + l0 + lw + (lane >> 2);
        float* dst = mh ? g_mpB : g_mpA;
        dst[r]     = rM  + flog2(rS);
        dst[r + 8] = rM1 + flog2(rS1);
    }
}

// ---------------------------------------------------------------------------
// Kernel C: partial attn over one l-half. Warp-private P fragments:
// mma1 D-frags -> ex2 in regs -> mma2 B-frags directly (no pt smem, no
// cross-warp dependency). Warp w owns m rows 16w..16w+15, all 128 c rows.
// grid (64, 4, 2), 128 thr, launch_bounds(128,3).
// smem: qt 16K | kt db 2x16K | vt 16K | mp 256B  (64.3KB -> 3 CTA/SM)
// ---------------------------------------------------------------------------
__global__ __launch_bounds__(128, 3) void attn_kernel()
{
    extern __shared__ char smc[];
    char* qt  = smc;
    char* kt0 = smc + 16384;
    char* kt1 = smc + 32768;
    char* vt  = smc + 49152;
    float* mp = (float*)(smc + 65536);
    uint32_t qtb = smem_u32(qt);
    uint32_t ktb[2] = {smem_u32(kt0), smem_u32(kt1)};
    uint32_t vtb = smem_u32(vt);

    int n = blockIdx.y, m0 = blockIdx.x * 64, t = threadIdx.x;
    int lh = blockIdx.z;
    int lbase = lh * 2048;
    int lane = t & 31, w = t >> 5;
    int lw = w * 16;
    int ecol = (lane & 3) * 2;

    // persistent qt (regular loads)
    const uint4* qsrc = (const uint4*)(g_qT + ((size_t)n * LL + m0) * CH);
#pragma unroll
    for (int i = t; i < 1024; i += 128) {
        int row = i >> 4, ch = i & 15;
        *(uint4*)(qt + swz(row, ch, 256)) = qsrc[row * 16 + ch];
    }

    const uint4* ksrc = (const uint4*)(g_kT + (size_t)n * LL * CH);
    const uint4* vsrc = (const uint4*)(g_vB + (size_t)n * CH * LL); // pitch 512 u4

    // prefetch kt chunk 0
#pragma unroll
    for (int i = t; i < 1024; i += 128) {
        int row = i >> 4, ch = i & 15;
        cpa16(ktb[0] + swz(row, ch, 256), &ksrc[(lbase + row) * 16 + ch]);
    }
    CPA_COMMIT();
    __syncthreads();

    // persistent qt A-fragments for this warp's 16 m-rows
    uint32_t af[8][4];
#pragma unroll
    for (int kk = 0; kk < 8; kk++) ldsm_x4(a_addr(qtb, lw, kk, lane, 256), af[kk]);

    // out accumulators: [c-tile 0..7][n-tile 0..1] -> 16x4 regs
    float oacc[16][4];
#pragma unroll
    for (int j = 0; j < 16; j++)
#pragma unroll
        for (int q = 0; q < 4; q++) oacc[j][q] = 0.f;

    for (int lc = 0; lc < 32; lc++) {
        __syncthreads();   // all warps done consuming vt & kt[(lc+1)&1]
        int lcur = lbase + lc * 64;
        // vt(lc): group V — overlaps mma1+exp
#pragma unroll
        for (int i = t; i < 1024; i += 128) {
            int row = i >> 3, ch = i & 7;
            cpa16(vtb + swz(row, ch, 128), &vsrc[row * 512 + (lcur >> 3) + ch]);
        }
        CPA_COMMIT();
        // kt(lc+1): group K — overlaps whole iteration
        if (lc < 31) {
            int lnext = lcur + 64;
#pragma unroll
            for (int i = t; i < 1024; i += 128) {
                int row = i >> 4, ch = i & 15;
                cpa16(ktb[(lc + 1) & 1] + swz(row, ch, 256), &ksrc[(lnext + row) * 16 + ch]);
            }
        }
        CPA_COMMIT();
        if (t < 64) {
            int gl = n * LL + lcur + t;
            float a = g_mpA[gl], b = g_mpB[gl];
            float mx = fmaxf(a, b), mn = fminf(a, b);
            mp[t] = mx + flog2(1.0f + fexp2(mn - mx));
        }
        CPA_WAIT(2);       // kt(lc) complete
        __syncthreads();   // kt(lc) + mp visible

        // mma1: S^T[m 16][l 64] = qt(regs) x kt
        uint32_t kb = ktb[lc & 1];
        float sacc[8][4];
#pragma unroll
        for (int j = 0; j < 8; j++)
#pragma unroll
            for (int q = 0; q < 4; q++) sacc[j][q] = 0.f;
#pragma unroll
        for (int kk = 0; kk < 8; kk++) {
#pragma unroll
            for (int jp = 0; jp < 4; jp++) {
                uint32_t b[4];
                ldsm_x4(b_addr(kb, jp * 16, kk, lane, 256), b);
                mma_bf16(sacc[jp * 2],     af[kk], b);
                mma_bf16(sacc[jp * 2 + 1], af[kk], b + 2);
            }
        }

        // exp in registers -> mma2 B-fragments (k=l, n=m). Warp-private.
        // bl[s] = n-tile m(lw..lw+7), bh[s] = n-tile m+8; s = l-16-block.
        uint32_t bl[4][2], bh[4][2];
#pragma unroll
        for (int j = 0; j < 8; j++) {
            int l = j * 8 + ecol;
            float mp0 = mp[l], mp1 = mp[l + 1];
            float e0 = fexp2(sacc[j][0] - mp0);
            float e1 = fexp2(sacc[j][1] - mp1);
            float e2 = fexp2(sacc[j][2] - mp0);
            float e3 = fexp2(sacc[j][3] - mp1);
            bl[j >> 1][j & 1] = pk_bf16(e0, e1);
            bh[j >> 1][j & 1] = pk_bf16(e2, e3);
        }

        CPA_WAIT(1);       // vt(lc) complete (kt(lc+1) may still fly)
        __syncthreads();   // vt visible

        // mma2: out[c 128][m 16] += v[c][l] * P^T[m][l]^T
#pragma unroll
        for (int s = 0; s < 4; s++) {
#pragma unroll
            for (int ct = 0; ct < 8; ct++) {
                uint32_t a[4];
                ldsm_x4(a_addr(vtb, ct * 16, s, lane, 128), a);
                mma_bf16(oacc[ct * 2],     a, bl[s]);
                mma_bf16(oacc[ct * 2 + 1], a, bh[s]);
            }
        }
    }

    // write partial: oacc[ct*2+nt]: c = ct*16 + lane>>2 (+8), m = m0+lw+nt*8+ecol(+1)
    float* pb = g_part + (size_t)lh * NB * CH * LL + (size_t)n * CH * LL;
#pragma unroll
    for (int ct = 0; ct < 8; ct++) {
        int c0 = ct * 16 + (lane >> 2);
#pragma unroll
        for (int nt = 0; nt < 2; nt++) {
            int mcol = m0 + lw + nt * 8 + ecol;
            float* d = oacc[ct * 2 + nt];
            *(float2*)(pb + (size_t)c0 * LL + mcol)       = make_float2(d[0], d[1]);
            *(float2*)(pb + (size_t)(c0 + 8) * LL + mcol) = make_float2(d[2], d[3]);
        }
    }
}

// ---------------------------------------------------------------------------
// Kernel D: out = x + part0 + part1
// ---------------------------------------------------------------------------
__global__ __launch_bounds__(256) void combine_kernel(
    const float* __restrict__ x, float* __restrict__ out)
{
    size_t i = ((size_t)blockIdx.x * 256 + threadIdx.x) * 4;
    float4 a = *(const float4*)(x + i);
    float4 b = *(const float4*)(g_part + i);
    float4 c = *(const float4*)(g_part + (size_t)NB * CH * LL + i);
    a.x += b.x + c.x; a.y += b.y + c.y; a.z += b.z + c.z; a.w += b.w + c.w;
    *(float4*)(out + i) = a;
}

// ---------------------------------------------------------------------------
extern "C" void kernel_launch(void* const* d_in, const int* in_sizes, int n_in,
                              void* d_out, int out_size)
{
    const float* x  = (const float*)d_in[0];
    const float* Wq = (const float*)d_in[1];
    const float* bq = (const float*)d_in[2];
    const float* Wk = (const float*)d_in[3];
    const float* bk = (const float*)d_in[4];
    const float* Wv = (const float*)d_in[5];
    const float* bv = (const float*)d_in[6];
    float* out = (float*)d_out;

    cudaFuncSetAttribute(qkv_kernel,   cudaFuncAttributeMaxDynamicSharedMemorySize, 49664);
    cudaFuncSetAttribute(stats_kernel, cudaFuncAttributeMaxDynamicSharedMemorySize, 49152);
    cudaFuncSetAttribute(attn_kernel,  cudaFuncAttributeMaxDynamicSharedMemorySize, 65792);

    xpose_kernel<<<dim3(128, 4), 256>>>(x);
    qkv_kernel<<<dim3(64, 4), 128, 49664>>>(Wq, bq, Wk, bk, Wv, bv);
    stats_kernel<<<dim3(64, 4, 2), 128, 49152>>>();
    attn_kernel<<<dim3(64, 4, 2), 128, 65792>>>();
    combine_kernel<<<(NB * CH * LL) / 1024, 256>>>(x, out);
}

// round 7
// speedup vs baseline: 6.9759x; 1.1082x over previous
#include <cuda_runtime.h>
#include <cuda_bf16.h>
#include <stdint.h>

#define NB 4
#define CH 128
#define LL 4096
// SCALE * log2(e): scores produced directly in log2 domain
#define SCALE_L2E ((float)(0.08838834764831845 * 1.4426950408889634))

// ---------------------------------------------------------------------------
// Scratch (allocation-free: static device globals)
// ---------------------------------------------------------------------------
__device__ __nv_bfloat16  g_xT[(size_t)NB * LL * CH];  // x^T [n][m][c]
__device__ __nv_bfloat16  g_qT[(size_t)NB * LL * CH];  // q^T [n][m][c]
__device__ __nv_bfloat16  g_kT[(size_t)NB * LL * CH];  // k^T [n][l][c], pre-scaled by SCALE*log2e
__device__ __nv_bfloat16  g_vB[(size_t)NB * CH * LL];  // v   [n][c][l]
__device__ __nv_bfloat16  g_s[(size_t)NB * LL * LL];   // raw scores S^T [n][m][l] bf16 (134MB)
__device__ float          g_mpA[NB * LL];              // m' for m-half 0 (log2 domain)
__device__ float          g_mpB[NB * LL];              // m' for m-half 1
__device__ float          g_mp [NB * LL];              // merged m'
__device__ float          g_part[2 * (size_t)NB * CH * LL]; // attn partials per l-half

// ---------------------------------------------------------------------------
// Helpers
// ---------------------------------------------------------------------------
__device__ __forceinline__ uint32_t smem_u32(const void* p) {
    uint32_t a;
    asm("{ .reg .u64 t; cvta.to.shared.u64 t, %1; cvt.u32.u64 %0, t; }"
        : "=r"(a) : "l"(p));
    return a;
}
__device__ __forceinline__ uint32_t pk_bf16(float a, float b) {
    __nv_bfloat162 t = __floats2bfloat162_rn(a, b);
    return *reinterpret_cast<uint32_t*>(&t);
}
__device__ __forceinline__ float fexp2(float x) {
    float y; asm("ex2.approx.f32 %0, %1;" : "=f"(y) : "f"(x)); return y;
}
__device__ __forceinline__ float flog2(float x) {
    float y; asm("lg2.approx.f32 %0, %1;" : "=f"(y) : "f"(x)); return y;
}

// Swizzled tile offset; pitch = bytes/row (256 for 128-bf16 rows, 128 for 64)
__device__ __forceinline__ uint32_t swz(int row, int ch, int pitch) {
    return (uint32_t)row * (uint32_t)pitch + (uint32_t)((ch ^ (row & 7)) << 4);
}
__device__ __forceinline__ void ldsm_x4(uint32_t addr, uint32_t* r) {
    asm volatile("ldmatrix.sync.aligned.m8n8.x4.shared.b16 {%0,%1,%2,%3}, [%4];"
        : "=r"(r[0]), "=r"(r[1]), "=r"(r[2]), "=r"(r[3]) : "r"(addr));
}
__device__ __forceinline__ uint32_t a_addr(uint32_t tb, int r0, int kk, int lane, int pitch) {
    return tb + swz(r0 + (lane & 15), kk * 2 + (lane >> 4), pitch);
}
__device__ __forceinline__ uint32_t b_addr(uint32_t tb, int n0, int kk, int lane, int pitch) {
    int g = lane >> 3;
    return tb + swz(n0 + (lane & 7) + ((g & 2) ? 8 : 0), kk * 2 + (g & 1), pitch);
}
__device__ __forceinline__ void mma_bf16(float* d, const uint32_t* a, const uint32_t* b) {
    asm volatile(
        "mma.sync.aligned.m16n8k16.row.col.f32.bf16.bf16.f32 "
        "{%0,%1,%2,%3}, {%4,%5,%6,%7}, {%8,%9}, {%0,%1,%2,%3};"
        : "+f"(d[0]), "+f"(d[1]), "+f"(d[2]), "+f"(d[3])
        : "r"(a[0]), "r"(a[1]), "r"(a[2]), "r"(a[3]), "r"(b[0]), "r"(b[1]));
}
__device__ __forceinline__ void cpa16(uint32_t dst, const void* src) {
    asm volatile("cp.async.cg.shared.global [%0], [%1], 16;" :: "r"(dst), "l"(src));
}
#define CPA_COMMIT() asm volatile("cp.async.commit_group;" ::: "memory")
#define CPA_WAIT(n)  asm volatile("cp.async.wait_group %0;" :: "n"(n) : "memory")

// ---------------------------------------------------------------------------
// Kernel 0: transpose+convert  x [n][c][m] fp32 -> g_xT [n][m][c] bf16
// ---------------------------------------------------------------------------
__global__ __launch_bounds__(256) void xpose_kernel(const float* __restrict__ x)
{
    __shared__ float ts[128][33];
    int n = blockIdx.y, m0 = blockIdx.x * 32, t = threadIdx.x;
    const float* xb = x + (size_t)n * CH * LL;
#pragma unroll
    for (int i = 0; i < 16; i++) {
        int c = i * 8 + (t >> 5);
        ts[c][t & 31] = xb[(size_t)c * LL + m0 + (t & 31)];
    }
    __syncthreads();
    int ml = t >> 3, cg = t & 7;
    __nv_bfloat16* dst = g_xT + ((size_t)n * LL + m0 + ml) * CH + cg * 16;
#pragma unroll
    for (int u = 0; u < 2; u++) {
        int cb = cg * 16 + u * 8;
        uint4 o;
        o.x = pk_bf16(ts[cb + 0][ml], ts[cb + 1][ml]);
        o.y = pk_bf16(ts[cb + 2][ml], ts[cb + 3][ml]);
        o.z = pk_bf16(ts[cb + 4][ml], ts[cb + 5][ml]);
        o.w = pk_bf16(ts[cb + 6][ml], ts[cb + 7][ml]);
        *(uint4*)(dst + u * 8) = o;
    }
}

// ---------------------------------------------------------------------------
// Kernel A: q/k/v via HMMA.  grid (64,4), 128 thr.
// ---------------------------------------------------------------------------
__global__ __launch_bounds__(128) void qkv_kernel(
    const float* __restrict__ Wq, const float* __restrict__ bq,
    const float* __restrict__ Wk, const float* __restrict__ bk,
    const float* __restrict__ Wv, const float* __restrict__ bv)
{
    extern __shared__ char smc[];
    char* xt = smc;
    char* wt = smc + 16384;
    float* bias = (float*)(smc + 49152);
    uint32_t xtb = smem_u32(xt), wtb = smem_u32(wt);
    int n = blockIdx.y, m0 = blockIdx.x * 64, t = threadIdx.x;
    int lane = t & 31, w = t >> 5;
    int ecol = (lane & 3) * 2;

    const uint4* xsrc = (const uint4*)(g_xT + ((size_t)n * LL + m0) * CH);
#pragma unroll
    for (int i = t; i < 1024; i += 128) {
        int row = i >> 4, ch = i & 15;
        *(uint4*)(xt + swz(row, ch, 256)) = xsrc[row * 16 + ch];
    }

    const float* Wm[3] = {Wq, Wk, Wv};
    const float* Bv[3] = {bq, bk, bv};

    for (int wi = 0; wi < 3; wi++) {
        __syncthreads();
#pragma unroll
        for (int i = t; i < 2048; i += 128) {
            int row = i >> 4, ch = i & 15;
            const float* src = Wm[wi] + row * 128 + ch * 8;
            float4 f0 = *(const float4*)src;
            float4 f1 = *(const float4*)(src + 4);
            uint4 u;
            u.x = pk_bf16(f0.x, f0.y); u.y = pk_bf16(f0.z, f0.w);
            u.z = pk_bf16(f1.x, f1.y); u.w = pk_bf16(f1.z, f1.w);
            *(uint4*)(wt + swz(row, ch, 256)) = u;
        }
        bias[t] = Bv[wi][t];
        __syncthreads();

        if (wi < 2) {
            int lw = w * 16;
            float sacc[16][4];
#pragma unroll
            for (int j = 0; j < 16; j++)
#pragma unroll
                for (int q = 0; q < 4; q++) sacc[j][q] = 0.f;
#pragma unroll
            for (int kk = 0; kk < 8; kk++) {
                uint32_t a[4];
                ldsm_x4(a_addr(xtb, lw, kk, lane, 256), a);
#pragma unroll
                for (int jp = 0; jp < 8; jp++) {
                    uint32_t b[4];
                    ldsm_x4(b_addr(wtb, jp * 16, kk, lane, 256), b);
                    mma_bf16(sacc[jp * 2],     a, b);
                    mma_bf16(sacc[jp * 2 + 1], a, b + 2);
                }
            }
            int mrow = m0 + lw + (lane >> 2);
            __nv_bfloat16* dst = (wi == 0 ? g_qT : g_kT) + (size_t)n * LL * CH;
            float sc = (wi == 0) ? 1.0f : SCALE_L2E;
#pragma unroll
            for (int j = 0; j < 16; j++) {
                int o = (j >> 1) * 16 + (j & 1) * 8 + ecol;
                float b0 = bias[o], b1 = bias[o + 1];
                *(uint32_t*)(dst + (size_t)mrow * CH + o) =
                    pk_bf16((sacc[j][0] + b0) * sc, (sacc[j][1] + b1) * sc);
                *(uint32_t*)(dst + (size_t)(mrow + 8) * CH + o) =
                    pk_bf16((sacc[j][2] + b0) * sc, (sacc[j][3] + b1) * sc);
            }
        } else {
            int rw2 = w * 32;
            float vacc[16][4];
#pragma unroll
            for (int j = 0; j < 16; j++)
#pragma unroll
                for (int q = 0; q < 4; q++) vacc[j][q] = 0.f;
#pragma unroll
            for (int kk = 0; kk < 8; kk++) {
                uint32_t a0[4], a1[4];
                ldsm_x4(a_addr(wtb, rw2,      kk, lane, 256), a0);
                ldsm_x4(a_addr(wtb, rw2 + 16, kk, lane, 256), a1);
#pragma unroll
                for (int bp = 0; bp < 4; bp++) {
                    uint32_t b[4];
                    ldsm_x4(b_addr(xtb, bp * 16, kk, lane, 256), b);
                    mma_bf16(vacc[bp * 2],         a0, b);
                    mma_bf16(vacc[bp * 2 + 1],     a0, b + 2);
                    mma_bf16(vacc[8 + bp * 2],     a1, b);
                    mma_bf16(vacc[8 + bp * 2 + 1], a1, b + 2);
                }
            }
#pragma unroll
            for (int set = 0; set < 2; set++) {
                int o = rw2 + set * 16 + (lane >> 2);
                float bo0 = bias[o], bo1 = bias[o + 8];
#pragma unroll
                for (int j = 0; j < 8; j++) {
                    int mc = m0 + j * 8 + ecol;
                    *(uint32_t*)(g_vB + ((size_t)n * CH + o) * LL + mc) =
                        pk_bf16(vacc[set * 8 + j][0] + bo0, vacc[set * 8 + j][1] + bo0);
                    *(uint32_t*)(g_vB + ((size_t)n * CH + o + 8) * LL + mc) =
                        pk_bf16(vacc[set * 8 + j][2] + bo1, vacc[set * 8 + j][3] + bo1);
                }
            }
        }
    }
}

// ---------------------------------------------------------------------------
// Kernel B: per-(l, m-half) stats in log2 domain + store S^T bf16 to g_s.
// grid (64, 4, 2), 128 thr. smem: kt 16K | qt db 2x16K | st 8K  (56K)
// ---------------------------------------------------------------------------
__global__ __launch_bounds__(128, 4) void stats_kernel()
{
    extern __shared__ char smc[];
    char* kt = smc;
    char* qt0 = smc + 16384;
    char* qt1 = smc + 32768;
    char* st  = smc + 49152;                // 8K transpose stage [m 64][l 64]
    uint32_t ktb = smem_u32(kt);
    uint32_t qtb[2] = {smem_u32(qt0), smem_u32(qt1)};
    uint32_t stb = smem_u32(st);

    int n = blockIdx.y, l0 = blockIdx.x * 64, t = threadIdx.x;
    int mh = blockIdx.z;
    int mbase = mh * 2048;
    int lane = t & 31, w = t >> 5;
    int lw = w * 16;
    int gid = lane >> 2, tig = lane & 3;

    const uint4* ksrc = (const uint4*)(g_kT + ((size_t)n * LL + l0) * CH);
#pragma unroll
    for (int i = t; i < 1024; i += 128) {
        int row = i >> 4, ch = i & 15;
        *(uint4*)(kt + swz(row, ch, 256)) = ksrc[row * 16 + ch];
    }

    const uint4* qsrc = (const uint4*)(g_qT + (size_t)n * LL * CH);
#pragma unroll
    for (int i = t; i < 1024; i += 128) {
        int row = i >> 4, ch = i & 15;
        cpa16(qtb[0] + swz(row, ch, 256), &qsrc[(mbase + row) * 16 + ch]);
    }
    CPA_COMMIT();
    __syncthreads();

    uint32_t af[8][4];
#pragma unroll
    for (int kk = 0; kk < 8; kk++) ldsm_x4(a_addr(ktb, lw, kk, lane, 256), af[kk]);

    float rM = -3.0e38f, rS = 0.f;
    float rM1 = -3.0e38f, rS1 = 0.f;

    int lA = lw + gid;          // l-local of d0/d1
    int lB = lA + 8;            // l-local of d2/d3
    uint4* gs4 = (uint4*)g_s;

    for (int mc = 0; mc < 32; mc++) {
        __syncthreads();
        if (mc < 31) {
            int mb = mbase + (mc + 1) * 64;
#pragma unroll
            for (int i = t; i < 1024; i += 128) {
                int row = i >> 4, ch = i & 15;
                cpa16(qtb[(mc + 1) & 1] + swz(row, ch, 256), &qsrc[(mb + row) * 16 + ch]);
            }
        }
        CPA_COMMIT();
        CPA_WAIT(1);
        __syncthreads();

        uint32_t qb = qtb[mc & 1];
        float sacc[8][4];
#pragma unroll
        for (int j = 0; j < 8; j++)
#pragma unroll
            for (int q = 0; q < 4; q++) sacc[j][q] = 0.f;
#pragma unroll
        for (int kk = 0; kk < 8; kk++) {
#pragma unroll
            for (int jp = 0; jp < 4; jp++) {
                uint32_t b[4];
                ldsm_x4(b_addr(qb, jp * 16, kk, lane, 256), b);
                mma_bf16(sacc[jp * 2],     af[kk], b);
                mma_bf16(sacc[jp * 2 + 1], af[kk], b + 2);
            }
        }

        // online stats
        float mx0 = -3.0e38f, mx1 = -3.0e38f;
#pragma unroll
        for (int j = 0; j < 8; j++) {
            mx0 = fmaxf(mx0, fmaxf(sacc[j][0], sacc[j][1]));
            mx1 = fmaxf(mx1, fmaxf(sacc[j][2], sacc[j][3]));
        }
        float nm0 = fmaxf(rM, mx0), nm1 = fmaxf(rM1, mx1);
        float s0 = 0.f, s1 = 0.f;
#pragma unroll
        for (int j = 0; j < 8; j++) {
            s0 += fexp2(sacc[j][0] - nm0) + fexp2(sacc[j][1] - nm0);
            s1 += fexp2(sacc[j][2] - nm1) + fexp2(sacc[j][3] - nm1);
        }
        rS  = rS  * fexp2(rM  - nm0) + s0; rM  = nm0;
        rS1 = rS1 * fexp2(rM1 - nm1) + s1; rM1 = nm1;

        // stage transposed S^T[m_loc][l_loc] bf16 into st (swizzled u16 stores)
#pragma unroll
        for (int j = 0; j < 8; j++) {
            int m0l = j * 8 + tig * 2;
            // addr(m,l) = m*128 + ((l>>3 ^ (m&7))<<4) + (l&7)*2
            uint32_t aA0 = (uint32_t)m0l * 128 + ((((uint32_t)lA >> 3) ^ (m0l & 7)) << 4) + (lA & 7) * 2;
            uint32_t aA1 = (uint32_t)(m0l + 1) * 128 + ((((uint32_t)lA >> 3) ^ ((m0l + 1) & 7)) << 4) + (lA & 7) * 2;
            uint32_t aB0 = (uint32_t)m0l * 128 + ((((uint32_t)lB >> 3) ^ (m0l & 7)) << 4) + (lB & 7) * 2;
            uint32_t aB1 = (uint32_t)(m0l + 1) * 128 + ((((uint32_t)lB >> 3) ^ ((m0l + 1) & 7)) << 4) + (lB & 7) * 2;
            *(__nv_bfloat16*)(st + aA0) = __float2bfloat16(sacc[j][0]);
            *(__nv_bfloat16*)(st + aA1) = __float2bfloat16(sacc[j][1]);
            *(__nv_bfloat16*)(st + aB0) = __float2bfloat16(sacc[j][2]);
            *(__nv_bfloat16*)(st + aB1) = __float2bfloat16(sacc[j][3]);
        }
        __syncthreads();

        // coalesced copy st -> g_s rows [m][l0..l0+64)
        int mg0 = mbase + mc * 64;
#pragma unroll
        for (int p = 0; p < 4; p++) {
            int idx = p * 128 + t;           // 512 chunks
            int mrow = idx >> 3, ch = idx & 7;
            uint4 u = *(uint4*)(st + swz(mrow, ch, 128));
            gs4[(((size_t)(n * LL + mg0 + mrow)) * LL + l0) / 8 + ch] = u;
        }
    }

#pragma unroll
    for (int d = 1; d < 4; d <<= 1) {
        float oM = __shfl_xor_sync(0xffffffffu, rM, d);
        float oS = __shfl_xor_sync(0xffffffffu, rS, d);
        float nm = fmaxf(rM, oM);
        rS = rS * fexp2(rM - nm) + oS * fexp2(oM - nm);
        rM = nm;
        oM = __shfl_xor_sync(0xffffffffu, rM1, d);
        oS = __shfl_xor_sync(0xffffffffu, rS1, d);
        nm = fmaxf(rM1, oM);
        rS1 = rS1 * fexp2(rM1 - nm) + oS * fexp2(oM - nm);
        rM1 = nm;
    }
    if (tig == 0) {
        int r = n * LL + l0 + lw + gid;
        float* dst = mh ? g_mpB : g_mpA;
        dst[r]     = rM  + flog2(rS);
        dst[r + 8] = rM1 + flog2(rS1);
    }
}

// ---------------------------------------------------------------------------
// Kernel B2: merge per-half stats -> g_mp
// ---------------------------------------------------------------------------
__global__ __launch_bounds__(256) void merge_mp_kernel()
{
    int i = blockIdx.x * 256 + threadIdx.x;
    float a = g_mpA[i], b = g_mpB[i];
    float mx = fmaxf(a, b), mn = fminf(a, b);
    g_mp[i] = mx + flog2(1.0f + fexp2(mn - mx));
}

// ---------------------------------------------------------------------------
// Kernel C: partial attn over one l-half, NO score recompute.
// Reads raw S^T tiles from g_s, exp on fragment registers, single mma chain.
// grid (64, 4, 2), 128 thr, launch_bounds(128,4).
// smem: st db 2x8K | vt db 2x16K | mp db 2x256  (49.7K -> 4 CTA/SM)
// ---------------------------------------------------------------------------
__global__ __launch_bounds__(128, 4) void attn_kernel()
{
    extern __shared__ char smc[];
    uint32_t base = smem_u32(smc);
    uint32_t stb[2] = {base, base + 8192};
    uint32_t vtb[2] = {base + 16384, base + 32768};
    float* mpf[2] = {(float*)(smc + 49152), (float*)(smc + 49408)};
    uint32_t mpb[2] = {base + 49152, base + 49408};

    int n = blockIdx.y, m0 = blockIdx.x * 64, t = threadIdx.x;
    int lh = blockIdx.z;
    int lbase = lh * 2048;
    int lane = t & 31, w = t >> 5;
    int lw = w * 16;
    int ecol = (lane & 3) * 2;

    const uint4* gs4  = (const uint4*)g_s;
    const uint4* vsrc = (const uint4*)(g_vB + (size_t)n * CH * LL); // pitch 512 u4
    const float* mpg  = g_mp + n * LL;

    // ---- load issuer for iteration i (one commit group) ----
    auto issue = [&](int i) {
        int buf = i & 1;
        int lcur = lbase + i * 64;
        // S tile: [m 64][l 64] rows from g_s
#pragma unroll
        for (int p = 0; p < 4; p++) {
            int idx = p * 128 + t;
            int row = idx >> 3, ch = idx & 7;
            cpa16(stb[buf] + swz(row, ch, 128),
                  &gs4[(((size_t)(n * LL + m0 + row)) * LL + lcur) / 8 + ch]);
        }
        // V tile: [c 128][l 64]
#pragma unroll
        for (int p = 0; p < 8; p++) {
            int idx = p * 128 + t;
            int row = idx >> 3, ch = idx & 7;
            cpa16(vtb[buf] + swz(row, ch, 128), &vsrc[row * 512 + (lcur >> 3) + ch]);
        }
        // mp chunk (64 floats)
        if (t < 16) cpa16(mpb[buf] + t * 16, mpg + lcur + t * 4);
        CPA_COMMIT();
    };

    issue(0);

    float oacc[16][4];
#pragma unroll
    for (int j = 0; j < 16; j++)
#pragma unroll
        for (int q = 0; q < 4; q++) oacc[j][q] = 0.f;

    for (int lc = 0; lc < 32; lc++) {
        CPA_WAIT(0);        // group lc arrived (only one in flight)
        __syncthreads();    // visibility + all warps done with buf (lc-1)
        if (lc < 31) issue(lc + 1);

        int buf = lc & 1;
        const float* mp = mpf[buf];

#pragma unroll
        for (int s = 0; s < 4; s++) {
            // raw S B-fragments for this warp's 16 m-rows, k-block s (16 l)
            uint32_t bb[4];
            ldsm_x4(b_addr(stb[buf], lw, s, lane, 128), bb);
            int l0s = s * 16 + ecol;
            float mpa = mp[l0s],     mpb_ = mp[l0s + 1];
            float mpc = mp[l0s + 8], mpd  = mp[l0s + 9];
            // exp on fragment registers: lo = even k, hi = odd k
#pragma unroll
            for (int r = 0; r < 4; r++) {
                float flo = __uint_as_float(bb[r] << 16);
                float fhi = __uint_as_float(bb[r] & 0xFFFF0000u);
                float s0 = (r & 1) ? mpc : mpa;
                float s1 = (r & 1) ? mpd : mpb_;
                bb[r] = pk_bf16(fexp2(flo - s0), fexp2(fhi - s1));
            }
            // mma2: out[c 128][m 16] += v[c][l16] * P
#pragma unroll
            for (int ct = 0; ct < 8; ct++) {
                uint32_t a[4];
                ldsm_x4(a_addr(vtb[buf], ct * 16, s, lane, 128), a);
                mma_bf16(oacc[ct * 2],     a, bb);
                mma_bf16(oacc[ct * 2 + 1], a, bb + 2);
            }
        }
    }

    // write partial: oacc[ct*2+nt]: c = ct*16 + lane>>2 (+8), m = m0+lw+nt*8+ecol(+1)
    float* pb = g_part + (size_t)lh * NB * CH * LL + (size_t)n * CH * LL;
#pragma unroll
    for (int ct = 0; ct < 8; ct++) {
        int c0 = ct * 16 + (lane >> 2);
#pragma unroll
        for (int nt = 0; nt < 2; nt++) {
            int mcol = m0 + lw + nt * 8 + ecol;
            float* d = oacc[ct * 2 + nt];
            *(float2*)(pb + (size_t)c0 * LL + mcol)       = make_float2(d[0], d[1]);
            *(float2*)(pb + (size_t)(c0 + 8) * LL + mcol) = make_float2(d[2], d[3]);
        }
    }
}

// ---------------------------------------------------------------------------
// Kernel D: out = x + part0 + part1
// ---------------------------------------------------------------------------
__global__ __launch_bounds__(256) void combine_kernel(
    const float* __restrict__ x, float* __restrict__ out)
{
    size_t i = ((size_t)blockIdx.x * 256 + threadIdx.x) * 4;
    float4 a = *(const float4*)(x + i);
    float4 b = *(const float4*)(g_part + i);
    float4 c = *(const float4*)(g_part + (size_t)NB * CH * LL + i);
    a.x += b.x + c.x; a.y += b.y + c.y; a.z += b.z + c.z; a.w += b.w + c.w;
    *(float4*)(out + i) = a;
}

// ---------------------------------------------------------------------------
extern "C" void kernel_launch(void* const* d_in, const int* in_sizes, int n_in,
                              void* d_out, int out_size)
{
    const float* x  = (const float*)d_in[0];
    const float* Wq = (const float*)d_in[1];
    const float* bq = (const float*)d_in[2];
    const float* Wk = (const float*)d_in[3];
    const float* bk = (const float*)d_in[4];
    const float* Wv = (const float*)d_in[5];
    const float* bv = (const float*)d_in[6];
    float* out = (float*)d_out;

    cudaFuncSetAttribute(qkv_kernel,   cudaFuncAttributeMaxDynamicSharedMemorySize, 49664);
    cudaFuncSetAttribute(stats_kernel, cudaFuncAttributeMaxDynamicSharedMemorySize, 57344);
    cudaFuncSetAttribute(attn_kernel,  cudaFuncAttributeMaxDynamicSharedMemorySize, 49664);

    xpose_kernel<<<dim3(128, 4), 256>>>(x);
    qkv_kernel<<<dim3(64, 4), 128, 49664>>>(Wq, bq, Wk, bk, Wv, bv);
    stats_kernel<<<dim3(64, 4, 2), 128, 57344>>>();
    merge_mp_kernel<<<(NB * LL) / 256, 256>>>();
    attn_kernel<<<dim3(64, 4, 2), 128, 49664>>>();
    combine_kernel<<<(NB * CH * LL) / 1024, 256>>>(x, out);
}

// round 8
// speedup vs baseline: 7.3005x; 1.0465x over previous
#include <cuda_runtime.h>
#include <cuda_bf16.h>
#include <stdint.h>

#define NB 4
#define CH 128
#define LL 4096
// SCALE * log2(e): scores produced directly in log2 domain
#define SCALE_L2E ((float)(0.08838834764831845 * 1.4426950408889634))

// ---------------------------------------------------------------------------
// Scratch (allocation-free: static device globals)
// ---------------------------------------------------------------------------
__device__ __nv_bfloat16  g_xT[(size_t)NB * LL * CH];  // x^T [n][m][c]
__device__ __nv_bfloat16  g_qT[(size_t)NB * LL * CH];  // q^T [n][m][c]
__device__ __nv_bfloat16  g_kT[(size_t)NB * LL * CH];  // k^T [n][l][c], pre-scaled by SCALE*log2e
__device__ __nv_bfloat16  g_vB[(size_t)NB * CH * LL];  // v   [n][c][l]
__device__ __nv_bfloat16  g_s[(size_t)NB * LL * LL];   // raw scores S^T [n][m][l] bf16 (134MB)
__device__ float          g_mpA[NB * LL];              // m' for m-half 0 (log2 domain)
__device__ float          g_mpB[NB * LL];              // m' for m-half 1
__device__ float          g_mp [NB * LL];              // merged m'
__device__ float          g_part[2 * (size_t)NB * CH * LL]; // attn partials per l-half

// ---------------------------------------------------------------------------
// Helpers
// ---------------------------------------------------------------------------
__device__ __forceinline__ uint32_t smem_u32(const void* p) {
    uint32_t a;
    asm("{ .reg .u64 t; cvta.to.shared.u64 t, %1; cvt.u32.u64 %0, t; }"
        : "=r"(a) : "l"(p));
    return a;
}
__device__ __forceinline__ uint32_t pk_bf16(float a, float b) {
    __nv_bfloat162 t = __floats2bfloat162_rn(a, b);
    return *reinterpret_cast<uint32_t*>(&t);
}
__device__ __forceinline__ float fexp2(float x) {
    float y; asm("ex2.approx.f32 %0, %1;" : "=f"(y) : "f"(x)); return y;
}
__device__ __forceinline__ float flog2(float x) {
    float y; asm("lg2.approx.f32 %0, %1;" : "=f"(y) : "f"(x)); return y;
}

// Swizzled tile offset; pitch = bytes/row (256 for 128-bf16 rows, 128 for 64)
__device__ __forceinline__ uint32_t swz(int row, int ch, int pitch) {
    return (uint32_t)row * (uint32_t)pitch + (uint32_t)((ch ^ (row & 7)) << 4);
}
__device__ __forceinline__ void ldsm_x4(uint32_t addr, uint32_t* r) {
    asm volatile("ldmatrix.sync.aligned.m8n8.x4.shared.b16 {%0,%1,%2,%3}, [%4];"
        : "=r"(r[0]), "=r"(r[1]), "=r"(r[2]), "=r"(r[3]) : "r"(addr));
}
__device__ __forceinline__ uint32_t a_addr(uint32_t tb, int r0, int kk, int lane, int pitch) {
    return tb + swz(r0 + (lane & 15), kk * 2 + (lane >> 4), pitch);
}
__device__ __forceinline__ uint32_t b_addr(uint32_t tb, int n0, int kk, int lane, int pitch) {
    int g = lane >> 3;
    return tb + swz(n0 + (lane & 7) + ((g & 2) ? 8 : 0), kk * 2 + (g & 1), pitch);
}
__device__ __forceinline__ void mma_bf16(float* d, const uint32_t* a, const uint32_t* b) {
    asm volatile(
        "mma.sync.aligned.m16n8k16.row.col.f32.bf16.bf16.f32 "
        "{%0,%1,%2,%3}, {%4,%5,%6,%7}, {%8,%9}, {%0,%1,%2,%3};"
        : "+f"(d[0]), "+f"(d[1]), "+f"(d[2]), "+f"(d[3])
        : "r"(a[0]), "r"(a[1]), "r"(a[2]), "r"(a[3]), "r"(b[0]), "r"(b[1]));
}
__device__ __forceinline__ void cpa16(uint32_t dst, const void* src) {
    asm volatile("cp.async.cg.shared.global [%0], [%1], 16;" :: "r"(dst), "l"(src));
}
#define CPA_COMMIT() asm volatile("cp.async.commit_group;" ::: "memory")
#define CPA_WAIT(n)  asm volatile("cp.async.wait_group %0;" :: "n"(n) : "memory")

// ---------------------------------------------------------------------------
// Kernel 0: transpose+convert  x [n][c][m] fp32 -> g_xT [n][m][c] bf16
// ---------------------------------------------------------------------------
__global__ __launch_bounds__(256) void xpose_kernel(const float* __restrict__ x)
{
    __shared__ float ts[128][33];
    int n = blockIdx.y, m0 = blockIdx.x * 32, t = threadIdx.x;
    const float* xb = x + (size_t)n * CH * LL;
#pragma unroll
    for (int i = 0; i < 16; i++) {
        int c = i * 8 + (t >> 5);
        ts[c][t & 31] = xb[(size_t)c * LL + m0 + (t & 31)];
    }
    __syncthreads();
    int ml = t >> 3, cg = t & 7;
    __nv_bfloat16* dst = g_xT + ((size_t)n * LL + m0 + ml) * CH + cg * 16;
#pragma unroll
    for (int u = 0; u < 2; u++) {
        int cb = cg * 16 + u * 8;
        uint4 o;
        o.x = pk_bf16(ts[cb + 0][ml], ts[cb + 1][ml]);
        o.y = pk_bf16(ts[cb + 2][ml], ts[cb + 3][ml]);
        o.z = pk_bf16(ts[cb + 4][ml], ts[cb + 5][ml]);
        o.w = pk_bf16(ts[cb + 6][ml], ts[cb + 7][ml]);
        *(uint4*)(dst + u * 8) = o;
    }
}

// ---------------------------------------------------------------------------
// Kernel A: q/k/v via HMMA.  grid (64,4), 128 thr.
// ---------------------------------------------------------------------------
__global__ __launch_bounds__(128) void qkv_kernel(
    const float* __restrict__ Wq, const float* __restrict__ bq,
    const float* __restrict__ Wk, const float* __restrict__ bk,
    const float* __restrict__ Wv, const float* __restrict__ bv)
{
    extern __shared__ char smc[];
    char* xt = smc;
    char* wt = smc + 16384;
    float* bias = (float*)(smc + 49152);
    uint32_t xtb = smem_u32(xt), wtb = smem_u32(wt);
    int n = blockIdx.y, m0 = blockIdx.x * 64, t = threadIdx.x;
    int lane = t & 31, w = t >> 5;
    int ecol = (lane & 3) * 2;

    const uint4* xsrc = (const uint4*)(g_xT + ((size_t)n * LL + m0) * CH);
#pragma unroll
    for (int i = t; i < 1024; i += 128) {
        int row = i >> 4, ch = i & 15;
        *(uint4*)(xt + swz(row, ch, 256)) = xsrc[row * 16 + ch];
    }

    const float* Wm[3] = {Wq, Wk, Wv};
    const float* Bv[3] = {bq, bk, bv};

    for (int wi = 0; wi < 3; wi++) {
        __syncthreads();
#pragma unroll
        for (int i = t; i < 2048; i += 128) {
            int row = i >> 4, ch = i & 15;
            const float* src = Wm[wi] + row * 128 + ch * 8;
            float4 f0 = *(const float4*)src;
            float4 f1 = *(const float4*)(src + 4);
            uint4 u;
            u.x = pk_bf16(f0.x, f0.y); u.y = pk_bf16(f0.z, f0.w);
            u.z = pk_bf16(f1.x, f1.y); u.w = pk_bf16(f1.z, f1.w);
            *(uint4*)(wt + swz(row, ch, 256)) = u;
        }
        bias[t] = Bv[wi][t];
        __syncthreads();

        if (wi < 2) {
            int lw = w * 16;
            float sacc[16][4];
#pragma unroll
            for (int j = 0; j < 16; j++)
#pragma unroll
                for (int q = 0; q < 4; q++) sacc[j][q] = 0.f;
#pragma unroll
            for (int kk = 0; kk < 8; kk++) {
                uint32_t a[4];
                ldsm_x4(a_addr(xtb, lw, kk, lane, 256), a);
#pragma unroll
                for (int jp = 0; jp < 8; jp++) {
                    uint32_t b[4];
                    ldsm_x4(b_addr(wtb, jp * 16, kk, lane, 256), b);
                    mma_bf16(sacc[jp * 2],     a, b);
                    mma_bf16(sacc[jp * 2 + 1], a, b + 2);
                }
            }
            int mrow = m0 + lw + (lane >> 2);
            __nv_bfloat16* dst = (wi == 0 ? g_qT : g_kT) + (size_t)n * LL * CH;
            float sc = (wi == 0) ? 1.0f : SCALE_L2E;
#pragma unroll
            for (int j = 0; j < 16; j++) {
                int o = (j >> 1) * 16 + (j & 1) * 8 + (lane & 3) * 2;
                float b0 = bias[o], b1 = bias[o + 1];
                *(uint32_t*)(dst + (size_t)mrow * CH + o) =
                    pk_bf16((sacc[j][0] + b0) * sc, (sacc[j][1] + b1) * sc);
                *(uint32_t*)(dst + (size_t)(mrow + 8) * CH + o) =
                    pk_bf16((sacc[j][2] + b0) * sc, (sacc[j][3] + b1) * sc);
            }
        } else {
            int rw2 = w * 32;
            float vacc[16][4];
#pragma unroll
            for (int j = 0; j < 16; j++)
#pragma unroll
                for (int q = 0; q < 4; q++) vacc[j][q] = 0.f;
#pragma unroll
            for (int kk = 0; kk < 8; kk++) {
                uint32_t a0[4], a1[4];
                ldsm_x4(a_addr(wtb, rw2,      kk, lane, 256), a0);
                ldsm_x4(a_addr(wtb, rw2 + 16, kk, lane, 256), a1);
#pragma unroll
                for (int bp = 0; bp < 4; bp++) {
                    uint32_t b[4];
                    ldsm_x4(b_addr(xtb, bp * 16, kk, lane, 256), b);
                    mma_bf16(vacc[bp * 2],         a0, b);
                    mma_bf16(vacc[bp * 2 + 1],     a0, b + 2);
                    mma_bf16(vacc[8 + bp * 2],     a1, b);
                    mma_bf16(vacc[8 + bp * 2 + 1], a1, b + 2);
                }
            }
#pragma unroll
            for (int set = 0; set < 2; set++) {
                int o = rw2 + set * 16 + (lane >> 2);
                float bo0 = bias[o], bo1 = bias[o + 8];
#pragma unroll
                for (int j = 0; j < 8; j++) {
                    int mc = m0 + j * 8 + (lane & 3) * 2;
                    *(uint32_t*)(g_vB + ((size_t)n * CH + o) * LL + mc) =
                        pk_bf16(vacc[set * 8 + j][0] + bo0, vacc[set * 8 + j][1] + bo0);
                    *(uint32_t*)(g_vB + ((size_t)n * CH + o + 8) * LL + mc) =
                        pk_bf16(vacc[set * 8 + j][2] + bo1, vacc[set * 8 + j][3] + bo1);
                }
            }
        }
    }
}

// ---------------------------------------------------------------------------
// Kernel B: stats + S^T store. CTA l-tile 128 (warp owns 32 l, A in regs,
// B-fragment reuse 4x). grid (32, 4, 2), 128 thr.
// smem: kt 32K | qt db 2x16K | st 16K  (80K -> 2 CTA/SM)
// ---------------------------------------------------------------------------
__global__ __launch_bounds__(128, 2) void stats_kernel()
{
    extern __shared__ char smc[];
    char* kt  = smc;                    // [l 128][c 128]
    char* qt0 = smc + 32768;
    char* qt1 = smc + 49152;
    char* st  = smc + 65536;            // stage [m 64][l 128] pitch 256
    uint32_t ktb = smem_u32(kt);
    uint32_t qtb[2] = {smem_u32(qt0), smem_u32(qt1)};

    int n = blockIdx.y, l0 = blockIdx.x * 128, t = threadIdx.x;
    int mh = blockIdx.z, mbase = mh * 2048;
    int lane = t & 31, w = t >> 5;
    int lw = w * 32;
    int gid = lane >> 2, tig = lane & 3;

    const uint4* ksrc = (const uint4*)(g_kT + ((size_t)n * LL + l0) * CH);
#pragma unroll
    for (int i = t; i < 2048; i += 128) {
        int row = i >> 4, ch = i & 15;
        *(uint4*)(kt + swz(row, ch, 256)) = ksrc[row * 16 + ch];
    }
    const uint4* qsrc = (const uint4*)(g_qT + (size_t)n * LL * CH);
#pragma unroll
    for (int i = t; i < 1024; i += 128) {
        int row = i >> 4, ch = i & 15;
        cpa16(qtb[0] + swz(row, ch, 256), &qsrc[(mbase + row) * 16 + ch]);
    }
    CPA_COMMIT();
    __syncthreads();

    // A fragments for this warp's 32 l-rows (2 x 16-row tiles), persistent
    uint32_t af[2][8][4];
#pragma unroll
    for (int lt = 0; lt < 2; lt++)
#pragma unroll
        for (int kk = 0; kk < 8; kk++)
            ldsm_x4(a_addr(ktb, lw + lt * 16, kk, lane, 256), af[lt][kk]);

    // online stats: [lt*2+half], row = lw + lt*16 + gid + half*8
    float rM[4], rS[4];
#pragma unroll
    for (int i = 0; i < 4; i++) { rM[i] = -3.0e38f; rS[i] = 0.f; }

    uint4* gs4 = (uint4*)g_s;

    for (int mc = 0; mc < 32; mc++) {
        __syncthreads();
        if (mc < 31) {
            int mb = mbase + (mc + 1) * 64;
#pragma unroll
            for (int i = t; i < 1024; i += 128) {
                int row = i >> 4, ch = i & 15;
                cpa16(qtb[(mc + 1) & 1] + swz(row, ch, 256), &qsrc[(mb + row) * 16 + ch]);
            }
        }
        CPA_COMMIT();
        CPA_WAIT(1);
        __syncthreads();

        uint32_t qb = qtb[mc & 1];
        float sacc[2][8][4];
#pragma unroll
        for (int lt = 0; lt < 2; lt++)
#pragma unroll
            for (int j = 0; j < 8; j++)
#pragma unroll
                for (int q = 0; q < 4; q++) sacc[lt][j][q] = 0.f;

#pragma unroll
        for (int kk = 0; kk < 8; kk++) {
#pragma unroll
            for (int jp = 0; jp < 4; jp++) {
                uint32_t b[4];
                ldsm_x4(b_addr(qb, jp * 16, kk, lane, 256), b);
                mma_bf16(sacc[0][jp * 2],     af[0][kk], b);
                mma_bf16(sacc[0][jp * 2 + 1], af[0][kk], b + 2);
                mma_bf16(sacc[1][jp * 2],     af[1][kk], b);
                mma_bf16(sacc[1][jp * 2 + 1], af[1][kk], b + 2);
            }
        }

        // online stats + stage S^T bf16
#pragma unroll
        for (int lt = 0; lt < 2; lt++) {
            float mx0 = -3.0e38f, mx1 = -3.0e38f;
#pragma unroll
            for (int j = 0; j < 8; j++) {
                mx0 = fmaxf(mx0, fmaxf(sacc[lt][j][0], sacc[lt][j][1]));
                mx1 = fmaxf(mx1, fmaxf(sacc[lt][j][2], sacc[lt][j][3]));
            }
            float nm0 = fmaxf(rM[lt * 2], mx0), nm1 = fmaxf(rM[lt * 2 + 1], mx1);
            float s0 = 0.f, s1 = 0.f;
#pragma unroll
            for (int j = 0; j < 8; j++) {
                s0 += fexp2(sacc[lt][j][0] - nm0) + fexp2(sacc[lt][j][1] - nm0);
                s1 += fexp2(sacc[lt][j][2] - nm1) + fexp2(sacc[lt][j][3] - nm1);
            }
            rS[lt * 2]     = rS[lt * 2]     * fexp2(rM[lt * 2]     - nm0) + s0;
            rM[lt * 2] = nm0;
            rS[lt * 2 + 1] = rS[lt * 2 + 1] * fexp2(rM[lt * 2 + 1] - nm1) + s1;
            rM[lt * 2 + 1] = nm1;

            int lA = lw + lt * 16 + gid;
            int lB = lA + 8;
#pragma unroll
            for (int j = 0; j < 8; j++) {
                int m0l = j * 8 + tig * 2;
                uint32_t aA0 = swz(m0l,     lA >> 3, 256) + (lA & 7) * 2;
                uint32_t aA1 = swz(m0l + 1, lA >> 3, 256) + (lA & 7) * 2;
                uint32_t aB0 = swz(m0l,     lB >> 3, 256) + (lB & 7) * 2;
                uint32_t aB1 = swz(m0l + 1, lB >> 3, 256) + (lB & 7) * 2;
                *(__nv_bfloat16*)(st + aA0) = __float2bfloat16(sacc[lt][j][0]);
                *(__nv_bfloat16*)(st + aA1) = __float2bfloat16(sacc[lt][j][1]);
                *(__nv_bfloat16*)(st + aB0) = __float2bfloat16(sacc[lt][j][2]);
                *(__nv_bfloat16*)(st + aB1) = __float2bfloat16(sacc[lt][j][3]);
            }
        }
        __syncthreads();

        // coalesced copy st -> g_s rows [m][l0..l0+128)
        int mg0 = mbase + mc * 64;
#pragma unroll
        for (int p = 0; p < 8; p++) {
            int idx = p * 128 + t;           // 1024 chunks
            int mrow = idx >> 4, ch = idx & 15;
            uint4 u = *(uint4*)(st + swz(mrow, ch, 256));
            gs4[(((size_t)(n * LL + mg0 + mrow)) * LL + l0) / 8 + ch] = u;
        }
    }

#pragma unroll
    for (int i = 0; i < 4; i++) {
#pragma unroll
        for (int d = 1; d < 4; d <<= 1) {
            float oM = __shfl_xor_sync(0xffffffffu, rM[i], d);
            float oS = __shfl_xor_sync(0xffffffffu, rS[i], d);
            float nm = fmaxf(rM[i], oM);
            rS[i] = rS[i] * fexp2(rM[i] - nm) + oS * fexp2(oM - nm);
            rM[i] = nm;
        }
    }
    if (tig == 0) {
        float* dst = mh ? g_mpB : g_mpA;
#pragma unroll
        for (int i = 0; i < 4; i++) {
            int r = n * LL + l0 + lw + (i >> 1) * 16 + gid + (i & 1) * 8;
            dst[r] = rM[i] + flog2(rS[i]);
        }
    }
}

// ---------------------------------------------------------------------------
// Kernel B2: merge per-half stats -> g_mp
// ---------------------------------------------------------------------------
__global__ __launch_bounds__(256) void merge_mp_kernel()
{
    int i = blockIdx.x * 256 + threadIdx.x;
    float a = g_mpA[i], b = g_mpB[i];
    float mx = fmaxf(a, b), mn = fminf(a, b);
    g_mp[i] = mx + flog2(1.0f + fexp2(mn - mx));
}

// ---------------------------------------------------------------------------
// Kernel C: partial attn. CTA m-tile 128 (warp owns 32 m -> A-fragment
// reuse 4x). grid (32, 4, 2), 128 thr, launch_bounds(128,2).
// smem: st db 2x16K | vt db 2x16K | mp db 2x256  (64.5K)
// ---------------------------------------------------------------------------
__global__ __launch_bounds__(128, 2) void attn_kernel()
{
    extern __shared__ char smc[];
    uint32_t base = smem_u32(smc);
    uint32_t stb[2] = {base, base + 16384};          // [m 128][l 64] pitch 128
    uint32_t vtb[2] = {base + 32768, base + 49152};  // [c 128][l 64] pitch 128
    float* mpf[2] = {(float*)(smc + 65536), (float*)(smc + 65792)};
    uint32_t mpb[2] = {base + 65536, base + 65792};

    int n = blockIdx.y, m0 = blockIdx.x * 128, t = threadIdx.x;
    int lh = blockIdx.z;
    int lbase = lh * 2048;
    int lane = t & 31, w = t >> 5;
    int mw = w * 32;
    int gid = lane >> 2, ecol = (lane & 3) * 2;

    const uint4* gs4  = (const uint4*)g_s;
    const uint4* vsrc = (const uint4*)(g_vB + (size_t)n * CH * LL); // pitch 512 u4
    const float* mpg  = g_mp + n * LL;

    auto issue = [&](int i) {
        int buf = i & 1;
        int lcur = lbase + i * 64;
        // S tile rows m0..m0+127
#pragma unroll
        for (int p = 0; p < 8; p++) {
            int idx = p * 128 + t;
            int row = idx >> 3, ch = idx & 7;
            cpa16(stb[buf] + swz(row, ch, 128),
                  &gs4[(((size_t)(n * LL + m0 + row)) * LL + lcur) / 8 + ch]);
        }
        // V tile
#pragma unroll
        for (int p = 0; p < 8; p++) {
            int idx = p * 128 + t;
            int row = idx >> 3, ch = idx & 7;
            cpa16(vtb[buf] + swz(row, ch, 128), &vsrc[row * 512 + (lcur >> 3) + ch]);
        }
        if (t < 16) cpa16(mpb[buf] + t * 16, mpg + lcur + t * 4);
        CPA_COMMIT();
    };

    issue(0);

    // oacc[ct][nt]: c = ct*16 + gid (+8), m = m0 + mw + nt*8 + ecol (+1)
    float oacc[8][4][4];
#pragma unroll
    for (int i = 0; i < 8; i++)
#pragma unroll
        for (int j = 0; j < 4; j++)
#pragma unroll
            for (int q = 0; q < 4; q++) oacc[i][j][q] = 0.f;

    for (int lc = 0; lc < 32; lc++) {
        CPA_WAIT(0);
        __syncthreads();
        if (lc < 31) issue(lc + 1);

        int buf = lc & 1;
        const float* mp = mpf[buf];

#pragma unroll
        for (int s = 0; s < 4; s++) {
            // P B-fragments for warp's 32 m-rows, k-block s (16 l)
            uint32_t bb[8];
            ldsm_x4(b_addr(stb[buf], mw,      s, lane, 128), bb);
            ldsm_x4(b_addr(stb[buf], mw + 16, s, lane, 128), bb + 4);
            int l0s = s * 16 + ecol;
            float mpa = mp[l0s],     mpb_ = mp[l0s + 1];
            float mpc = mp[l0s + 8], mpd  = mp[l0s + 9];
#pragma unroll
            for (int r = 0; r < 8; r++) {
                float flo = __uint_as_float(bb[r] << 16);
                float fhi = __uint_as_float(bb[r] & 0xFFFF0000u);
                float s0 = (r & 1) ? mpc : mpa;
                float s1 = (r & 1) ? mpd : mpb_;
                bb[r] = pk_bf16(fexp2(flo - s0), fexp2(fhi - s1));
            }
            // mma: out[c 128][m 32] += v[c][l16] * P ; A reuse 4x
#pragma unroll
            for (int ct = 0; ct < 8; ct++) {
                uint32_t a[4];
                ldsm_x4(a_addr(vtb[buf], ct * 16, s, lane, 128), a);
                mma_bf16(oacc[ct][0], a, bb);
                mma_bf16(oacc[ct][1], a, bb + 2);
                mma_bf16(oacc[ct][2], a, bb + 4);
                mma_bf16(oacc[ct][3], a, bb + 6);
            }
        }
    }

    float* pb = g_part + (size_t)lh * NB * CH * LL + (size_t)n * CH * LL;
#pragma unroll
    for (int ct = 0; ct < 8; ct++) {
        int c0 = ct * 16 + gid;
#pragma unroll
        for (int nt = 0; nt < 4; nt++) {
            int mcol = m0 + mw + nt * 8 + ecol;
            float* d = oacc[ct][nt];
            *(float2*)(pb + (size_t)c0 * LL + mcol)       = make_float2(d[0], d[1]);
            *(float2*)(pb + (size_t)(c0 + 8) * LL + mcol) = make_float2(d[2], d[3]);
        }
    }
}

// ---------------------------------------------------------------------------
// Kernel D: out = x + part0 + part1
// ---------------------------------------------------------------------------
__global__ __launch_bounds__(256) void combine_kernel(
    const float* __restrict__ x, float* __restrict__ out)
{
    size_t i = ((size_t)blockIdx.x * 256 + threadIdx.x) * 4;
    float4 a = *(const float4*)(x + i);
    float4 b = *(const float4*)(g_part + i);
    float4 c = *(const float4*)(g_part + (size_t)NB * CH * LL + i);
    a.x += b.x + c.x; a.y += b.y + c.y; a.z += b.z + c.z; a.w += b.w + c.w;
    *(float4*)(out + i) = a;
}

// ---------------------------------------------------------------------------
extern "C" void kernel_launch(void* const* d_in, const int* in_sizes, int n_in,
                              void* d_out, int out_size)
{
    const float* x  = (const float*)d_in[0];
    const float* Wq = (const float*)d_in[1];
    const float* bq = (const float*)d_in[2];
    const float* Wk = (const float*)d_in[3];
    const float* bk = (const float*)d_in[4];
    const float* Wv = (const float*)d_in[5];
    const float* bv = (const float*)d_in[6];
    float* out = (float*)d_out;

    cudaFuncSetAttribute(qkv_kernel,   cudaFuncAttributeMaxDynamicSharedMemorySize, 49664);
    cudaFuncSetAttribute(stats_kernel, cudaFuncAttributeMaxDynamicSharedMemorySize, 81920);
    cudaFuncSetAttribute(attn_kernel,  cudaFuncAttributeMaxDynamicSharedMemorySize, 66048);

    xpose_kernel<<<dim3(128, 4), 256>>>(x);
    qkv_kernel<<<dim3(64, 4), 128, 49664>>>(Wq, bq, Wk, bk, Wv, bv);
    stats_kernel<<<dim3(32, 4, 2), 128, 81920>>>();
    merge_mp_kernel<<<(NB * LL) / 256, 256>>>();
    attn_kernel<<<dim3(32, 4, 2), 128, 66048>>>();
    combine_kernel<<<(NB * CH * LL) / 1024, 256>>>(x, out);
}